// round 5
// baseline (speedup 1.0000x reference)
#include <cuda_runtime.h>
#include <math.h>

#define BB 256
#define TT 20
#define DD 128
#define HH 256
#define KSZ 256
#define MEMN 20
#define YY 4
#define EPSF 1e-8f
#define NFRM (BB*TT)
#define GSPL 8

// ---------------- device scratch ----------------
__device__ float g_h3[NFRM*512];
__device__ float g_fc1p[2*NFRM*256];    // fc1 split-K partials
__device__ float g_fc2p[2*NFRM*DD];     // fc2 split-K partials
__device__ float g_z[NFRM*DD];
__device__ float g_gz[NFRM*1024];       // precomputed z@Wz^T + b
__device__ float g_gates8[GSPL*BB*1024];// gates split-K partials
__device__ float g_hpart[4*BB*768];     // heads split-K partials
__device__ float g_hst[BB*HH];
__device__ float g_cst[BB*HH];
__device__ float g_r[BB*KSZ];
__device__ float g_M[BB*MEMN*KSZ];
__device__ float g_Wcat[1024*512];      // [Wr | Wh]
__device__ float g_Wz[1024*128];
__device__ float g_Whead[768*256];

__device__ __forceinline__ float sigmf(float x){ return 1.f/(1.f+expf(-x)); }

// ---------------- fused conv encoder: one frame per block ----------------
#define S_IN 0
#define S_H1 1156
#define S_H2 12676
#define CONV_SMEM_FLOATS 16516

__global__ void __launch_bounds__(256, 3) k_conv(
    const float* __restrict__ x,
    const float* __restrict__ w1, const float* __restrict__ b1,
    const float* __restrict__ w2, const float* __restrict__ b2,
    const float* __restrict__ w3, const float* __restrict__ b3)
{
    extern __shared__ float sm[];
    float* s_in = sm + S_IN;
    float* s_h1 = sm + S_H1;
    float* s_h2 = sm + S_H2;
    const int f   = blockIdx.x;
    const int tid = threadIdx.x;

    for (int i = tid; i < CONV_SMEM_FLOATS; i += 256) sm[i] = 0.f;
    __syncthreads();
    for (int i = tid; i < 1024; i += 256) {
        int iy = i >> 5, ix = i & 31;
        s_in[(iy+1)*34 + ix + 1] = x[f*1024 + i];
    }
    __syncthreads();

    // ---- conv1: 1->32ch, 32x32 -> 16x16 ----
    for (int p = tid; p < 32*16; p += 256) {
        int oc = p >> 4, oy = p & 15;
        float bias = __ldg(b1 + oc);
        float acc[16];
        #pragma unroll
        for (int ox = 0; ox < 16; ox++) acc[ox] = bias;
        #pragma unroll
        for (int kh = 0; kh < 4; kh++) {
            const float* row = s_in + (2*oy+kh)*34;
            const float4 w = __ldg((const float4*)(w1 + oc*16 + kh*4));
            #pragma unroll
            for (int ox = 0; ox < 16; ox++) {
                acc[ox] += row[2*ox]*w.x + row[2*ox+1]*w.y
                         + row[2*ox+2]*w.z + row[2*ox+3]*w.w;
            }
        }
        float* dst = s_h1 + oc*360 + (oy+1)*20 + 1;
        #pragma unroll
        for (int ox = 0; ox < 16; ox++) dst[ox] = fmaxf(acc[ox], 0.f);
    }
    __syncthreads();

    // ---- conv2: 32->32ch, 16x16 -> 8x8; 128 threads (2 oc x 8 ox per thread) ----
    if (tid < 128) {
        int ocp = tid >> 3;
        int oy  = tid & 7;
        int oc0 = ocp*2, oc1 = oc0 + 1;
        float bv0 = __ldg(b2 + oc0), bv1 = __ldg(b2 + oc1);
        float acc0[8] = {bv0,bv0,bv0,bv0,bv0,bv0,bv0,bv0};
        float acc1[8] = {bv1,bv1,bv1,bv1,bv1,bv1,bv1,bv1};
        for (int ic = 0; ic < 32; ic++) {
            const float* chan = s_h1 + ic*360;
            #pragma unroll
            for (int kh = 0; kh < 4; kh++) {
                const float* row = chan + (2*oy+kh)*20;
                float4 r0 = *(const float4*)(row);
                float4 r1 = *(const float4*)(row+4);
                float4 r2 = *(const float4*)(row+8);
                float4 r3 = *(const float4*)(row+12);
                float2 r4 = *(const float2*)(row+16);
                float rr[18] = {r0.x,r0.y,r0.z,r0.w, r1.x,r1.y,r1.z,r1.w,
                                r2.x,r2.y,r2.z,r2.w, r3.x,r3.y,r3.z,r3.w,
                                r4.x,r4.y};
                const float4 wa = __ldg((const float4*)(w2 + oc0*512 + ic*16 + kh*4));
                const float4 wb = __ldg((const float4*)(w2 + oc1*512 + ic*16 + kh*4));
                #pragma unroll
                for (int ox = 0; ox < 8; ox++) {
                    acc0[ox] += rr[2*ox]*wa.x + rr[2*ox+1]*wa.y
                              + rr[2*ox+2]*wa.z + rr[2*ox+3]*wa.w;
                    acc1[ox] += rr[2*ox]*wb.x + rr[2*ox+1]*wb.y
                              + rr[2*ox+2]*wb.z + rr[2*ox+3]*wb.w;
                }
            }
        }
        float* d0 = s_h2 + oc0*120 + (oy+1)*12 + 1;
        float* d1 = s_h2 + oc1*120 + (oy+1)*12 + 1;
        #pragma unroll
        for (int ox = 0; ox < 8; ox++) {
            d0[ox] = fmaxf(acc0[ox], 0.f);
            d1[ox] = fmaxf(acc1[ox], 0.f);
        }
    }
    __syncthreads();

    // ---- conv3: 32->32ch, 8x8 -> 4x4 ----
    {
        int oc = tid >> 3, oy = (tid >> 1) & 3, q = tid & 1;
        float bias = __ldg(b3 + oc);
        float acc0 = bias, acc1 = bias;
        for (int ic = 0; ic < 32; ic++) {
            const float* chan = s_h2 + ic*120;
            #pragma unroll
            for (int kh = 0; kh < 4; kh++) {
                const float* row = chan + (2*oy+kh)*12 + 4*q;
                float4 a = *(const float4*)(row);
                float4 b = *(const float4*)(row+4);
                const float4 w = __ldg((const float4*)(w3 + oc*512 + ic*16 + kh*4));
                acc0 += a.x*w.x + a.y*w.y + a.z*w.z + a.w*w.w;
                acc1 += a.z*w.x + a.w*w.y + b.x*w.z + b.y*w.w;
            }
        }
        int base = f*512 + oc*16 + oy*4 + 2*q;
        g_h3[base]   = fmaxf(acc0, 0.f);
        g_h3[base+1] = fmaxf(acc1, 0.f);
    }
}

// ---------------- full-K GEMM: C = act(A @ W^T + bias), 64x64 tiles ----------------
__global__ void __launch_bounds__(256, 2) k_gemm(
    const float* __restrict__ A, int lda,
    const float* __restrict__ W, int ldw,
    const float* __restrict__ bias,
    float* __restrict__ C, int ldc, int K, int act)
{
    __shared__ float sA[2][16][68];
    __shared__ float sW[2][16][68];
    int tid = threadIdx.x;
    int tx = tid & 15, ty = tid >> 4;
    int lr = tid >> 2;
    int lk = (tid & 3) << 2;
    const float* Ab = A + (blockIdx.y*64 + lr)*lda + lk;
    const float* Wb = W + (blockIdx.x*64 + lr)*ldw + lk;

    float acc[4][4];
    #pragma unroll
    for (int i = 0; i < 4; i++)
        #pragma unroll
        for (int j = 0; j < 4; j++) acc[i][j] = 0.f;

    int nk = K >> 4;
    float4 a4 = *(const float4*)(Ab);
    float4 w4 = *(const float4*)(Wb);
    sA[0][lk+0][lr] = a4.x; sA[0][lk+1][lr] = a4.y; sA[0][lk+2][lr] = a4.z; sA[0][lk+3][lr] = a4.w;
    sW[0][lk+0][lr] = w4.x; sW[0][lk+1][lr] = w4.y; sW[0][lk+2][lr] = w4.z; sW[0][lk+3][lr] = w4.w;
    __syncthreads();

    for (int kb = 0; kb < nk; kb++) {
        int s = kb & 1;
        float4 na, nw;
        if (kb + 1 < nk) {
            na = *(const float4*)(Ab + ((kb+1) << 4));
            nw = *(const float4*)(Wb + ((kb+1) << 4));
        }
        #pragma unroll
        for (int kk = 0; kk < 16; kk++) {
            float4 av = *(const float4*)&sA[s][kk][ty<<2];
            float4 wv = *(const float4*)&sW[s][kk][tx<<2];
            float a[4] = {av.x, av.y, av.z, av.w};
            float w[4] = {wv.x, wv.y, wv.z, wv.w};
            #pragma unroll
            for (int i = 0; i < 4; i++)
                #pragma unroll
                for (int j = 0; j < 4; j++) acc[i][j] += a[i]*w[j];
        }
        if (kb + 1 < nk) {
            int d = s ^ 1;
            sA[d][lk+0][lr] = na.x; sA[d][lk+1][lr] = na.y; sA[d][lk+2][lr] = na.z; sA[d][lk+3][lr] = na.w;
            sW[d][lk+0][lr] = nw.x; sW[d][lk+1][lr] = nw.y; sW[d][lk+2][lr] = nw.z; sW[d][lk+3][lr] = nw.w;
            __syncthreads();
        }
    }
    int rb = blockIdx.y*64 + (ty<<2);
    int cb = blockIdx.x*64 + (tx<<2);
    #pragma unroll
    for (int i = 0; i < 4; i++)
        #pragma unroll
        for (int j = 0; j < 4; j++) {
            float v = acc[i][j] + bias[cb+j];
            if (act == 1) v = fmaxf(v, 0.f);
            C[(rb+i)*ldc + cb + j] = v;
        }
}

// ---------------- split-K partial GEMM: Cpart[z] = Aslice @ Wslice^T ----------------
// mode 0: plain A (lda). mode 1: A row b = [r(b,:), h(b,:)] (512 cols).
// mode 2: A = relu(fc1p0 + fc1p1 + abias) gathered from g_fc1p (256 cols).
__global__ void __launch_bounds__(256, 2) k_gemm_part(
    const float* __restrict__ A, int lda,
    const float* __restrict__ W, int ldw,
    const float* __restrict__ abias,
    float* __restrict__ C, int ldc,
    int Ksplit, int partStride, int mode)
{
    __shared__ float sA[2][16][68];
    __shared__ float sW[2][16][68];
    int tid = threadIdx.x;
    int tx = tid & 15, ty = tid >> 4;
    int lr = tid >> 2;
    int lk = (tid & 3) << 2;
    int z = blockIdx.z;
    int kStart = z * Ksplit;
    int rowA = blockIdx.y*64 + lr;
    const float* Wb = W + (blockIdx.x*64 + lr)*ldw + kStart + lk;
    float* Cp = C + z * partStride;

    auto ldA = [&](int k0) -> float4 {
        int c = kStart + k0 + lk;
        if (mode == 0) return *(const float4*)(A + rowA*lda + c);
        if (mode == 1) {
            if (c < KSZ) return *(const float4*)(g_r + rowA*KSZ + c);
            return *(const float4*)(g_hst + rowA*HH + (c - KSZ));
        }
        // mode 2: combine fc1 partials + bias + relu
        float4 p0 = *(const float4*)(g_fc1p + rowA*256 + c);
        float4 p1 = *(const float4*)(g_fc1p + NFRM*256 + rowA*256 + c);
        float4 bb = *(const float4*)(abias + c);
        float4 r;
        r.x = fmaxf(p0.x + p1.x + bb.x, 0.f);
        r.y = fmaxf(p0.y + p1.y + bb.y, 0.f);
        r.z = fmaxf(p0.z + p1.z + bb.z, 0.f);
        r.w = fmaxf(p0.w + p1.w + bb.w, 0.f);
        return r;
    };

    float acc[4][4];
    #pragma unroll
    for (int i = 0; i < 4; i++)
        #pragma unroll
        for (int j = 0; j < 4; j++) acc[i][j] = 0.f;

    int nk = Ksplit >> 4;
    float4 a4 = ldA(0);
    float4 w4 = *(const float4*)(Wb);
    sA[0][lk+0][lr] = a4.x; sA[0][lk+1][lr] = a4.y; sA[0][lk+2][lr] = a4.z; sA[0][lk+3][lr] = a4.w;
    sW[0][lk+0][lr] = w4.x; sW[0][lk+1][lr] = w4.y; sW[0][lk+2][lr] = w4.z; sW[0][lk+3][lr] = w4.w;
    __syncthreads();

    for (int kb = 0; kb < nk; kb++) {
        int s = kb & 1;
        float4 na, nw;
        if (kb + 1 < nk) {
            na = ldA((kb+1) << 4);
            nw = *(const float4*)(Wb + ((kb+1) << 4));
        }
        #pragma unroll
        for (int kk = 0; kk < 16; kk++) {
            float4 av = *(const float4*)&sA[s][kk][ty<<2];
            float4 wv = *(const float4*)&sW[s][kk][tx<<2];
            float a[4] = {av.x, av.y, av.z, av.w};
            float w[4] = {wv.x, wv.y, wv.z, wv.w};
            #pragma unroll
            for (int i = 0; i < 4; i++)
                #pragma unroll
                for (int j = 0; j < 4; j++) acc[i][j] += a[i]*w[j];
        }
        if (kb + 1 < nk) {
            int d = s ^ 1;
            sA[d][lk+0][lr] = na.x; sA[d][lk+1][lr] = na.y; sA[d][lk+2][lr] = na.z; sA[d][lk+3][lr] = na.w;
            sW[d][lk+0][lr] = nw.x; sW[d][lk+1][lr] = nw.y; sW[d][lk+2][lr] = nw.z; sW[d][lk+3][lr] = nw.w;
            __syncthreads();
        }
    }
    int rb = blockIdx.y*64 + (ty<<2);
    int cb = blockIdx.x*64 + (tx<<2);
    #pragma unroll
    for (int i = 0; i < 4; i++)
        #pragma unroll
        for (int j = 0; j < 4; j++)
            Cp[(rb+i)*ldc + cb + j] = acc[i][j];
}

// ---------------- context norm over time, fused fc2 combine + bias + relu ------------
__global__ void k_ctxnorm(const float* __restrict__ fc2b,
                          const float* __restrict__ gamma, const float* __restrict__ beta)
{
    int b = blockIdx.x, d = threadIdx.x;
    float bias = fc2b[d];
    float v[TT];
    float s = 0.f, s2 = 0.f;
    #pragma unroll
    for (int t = 0; t < TT; t++) {
        int idx = (b*TT+t)*DD + d;
        v[t] = fmaxf(g_fc2p[idx] + g_fc2p[NFRM*DD + idx] + bias, 0.f);
        s += v[t]; s2 += v[t]*v[t];
    }
    float mu  = s / TT;
    float var = (s2 - TT*mu*mu) / (TT - 1);
    float inv = 1.f / sqrtf(var + EPSF);
    float ga = gamma[d], be = beta[d];
    #pragma unroll
    for (int t = 0; t < TT; t++)
        g_z[(b*TT+t)*DD + d] = (v[t] - mu)*inv*ga + be;
}

// ---------------- setup ----------------
__global__ void k_setup(const float* __restrict__ mem0,
                        const float* __restrict__ wi, const float* __restrict__ wh,
                        const float* __restrict__ wk, const float* __restrict__ wwk,
                        const float* __restrict__ wv,
                        float* __restrict__ out, int out_size)
{
    int i = blockIdx.x*256 + threadIdx.x;
    if (i < BB*MEMN*KSZ) g_M[i] = mem0[i % (MEMN*KSZ)];
    if (i < 1024*512) {
        int j = i >> 9, c = i & 511;
        g_Wcat[i] = (c < 256) ? wi[j*384 + 128 + c] : wh[j*256 + (c-256)];
    }
    if (i < 1024*128) {
        int j = i >> 7, c = i & 127;
        g_Wz[i] = wi[j*384 + c];
    }
    if (i < 768*256) {
        int n = i >> 8;
        g_Whead[i] = (n < 256) ? wk[i] : ((n < 512) ? wwk[i - 256*256] : wv[i - 512*256]);
    }
    if (i < BB*HH) { g_hst[i] = 0.f; g_cst[i] = 0.f; }
    if (i < BB*KSZ) g_r[i] = 0.f;
    if (i < out_size) out[i] = 0.f;
}

// ---------------- per-step: LSTM update (sums gz + 8 gate partials, float4) ----------
__global__ void k_lstm(int t)
{
    int idx = blockIdx.x*256 + threadIdx.x;   // BB*64 threads, 4 j's each
    int b = idx >> 6, j = (idx & 63) << 2;
    const float* gz = g_gz + (b*TT + t)*1024;
    float4 g[4];
    #pragma unroll
    for (int gt = 0; gt < 4; gt++) g[gt] = *(const float4*)(gz + gt*256 + j);
    #pragma unroll
    for (int z = 0; z < GSPL; z++) {
        const float* gp = g_gates8 + z*(BB*1024) + b*1024;
        #pragma unroll
        for (int gt = 0; gt < 4; gt++) {
            float4 p = *(const float4*)(gp + gt*256 + j);
            g[gt].x += p.x; g[gt].y += p.y; g[gt].z += p.z; g[gt].w += p.w;
        }
    }
    float4 c = *(const float4*)(g_cst + b*HH + j);
    float4 cn, hn;
    cn.x = sigmf(g[1].x)*c.x + sigmf(g[0].x)*tanhf(g[2].x);
    cn.y = sigmf(g[1].y)*c.y + sigmf(g[0].y)*tanhf(g[2].y);
    cn.z = sigmf(g[1].z)*c.z + sigmf(g[0].z)*tanhf(g[2].z);
    cn.w = sigmf(g[1].w)*c.w + sigmf(g[0].w)*tanhf(g[2].w);
    hn.x = sigmf(g[3].x)*tanhf(cn.x);
    hn.y = sigmf(g[3].y)*tanhf(cn.y);
    hn.z = sigmf(g[3].z)*tanhf(cn.z);
    hn.w = sigmf(g[3].w)*tanhf(cn.w);
    *(float4*)(g_cst + b*HH + j) = cn;
    *(float4*)(g_hst + b*HH + j) = hn;
}

// ---------------- per-step: memory read/write + (last step) output ----------------
__global__ void __launch_bounds__(256) k_mem(int t, const float* __restrict__ wo,
                                             const float* __restrict__ wob,
                                             float* __restrict__ out, int out_size)
{
    __shared__ float s_kr[256], s_kw[256], s_rnew[256];
    __shared__ float s_simr[MEMN], s_simw[MEMN];
    __shared__ float s_wr[4], s_ws[4];
    __shared__ int   s_ir[4], s_iw[4];
    __shared__ float s_red[16];
    __shared__ float s_nrm[2];
    __shared__ float s_y[4];

    int b = blockIdx.x, tid = threadIdx.x;
    int lane = tid & 31, wid = tid >> 5;

    float kr = 0.f, kw = 0.f, vvs = 0.f;
    #pragma unroll
    for (int z = 0; z < 4; z++) {
        const float* hp = g_hpart + z*(BB*768) + b*768;
        kr  += hp[tid];
        kw  += hp[256 + tid];
        vvs += hp[512 + tid];
    }
    float vv = tanhf(vvs);
    s_kr[tid] = kr;
    s_kw[tid] = kw;

    float pr = kr*kr, pw = kw*kw;
    #pragma unroll
    for (int o = 16; o > 0; o >>= 1) {
        pr += __shfl_xor_sync(0xffffffffu, pr, o);
        pw += __shfl_xor_sync(0xffffffffu, pw, o);
    }
    if (lane == 0) { s_red[wid] = pr; s_red[8 + wid] = pw; }
    __syncthreads();
    if (tid == 0) {
        float sr = 0.f, sw = 0.f;
        #pragma unroll
        for (int w = 0; w < 8; w++) { sr += s_red[w]; sw += s_red[8 + w]; }
        s_nrm[0] = 1.f / (sqrtf(sr) + EPSF);
        s_nrm[1] = 1.f / (sqrtf(sw) + EPSF);
    }
    __syncthreads();

    for (int n = wid; n < MEMN; n += 8) {
        const float* Mr = g_M + (b*MEMN + n)*KSZ;
        float dr = 0.f, dw = 0.f, nn = 0.f;
        #pragma unroll
        for (int d0 = 0; d0 < KSZ; d0 += 32) {
            float m = Mr[d0 + lane];
            dr += s_kr[d0 + lane]*m;
            dw += s_kw[d0 + lane]*m;
            nn += m*m;
        }
        #pragma unroll
        for (int o = 16; o > 0; o >>= 1) {
            dr += __shfl_xor_sync(0xffffffffu, dr, o);
            dw += __shfl_xor_sync(0xffffffffu, dw, o);
            nn += __shfl_xor_sync(0xffffffffu, nn, o);
        }
        if (lane == 0) {
            float mi = 1.f / (sqrtf(nn) + EPSF);
            s_simr[n] = dr * s_nrm[0] * mi;
            s_simw[n] = dw * s_nrm[1] * mi;
        }
    }
    __syncthreads();

    if (tid < 2) {
        const float* sims = tid ? s_simw : s_simr;
        float* wout = tid ? s_ws : s_wr;
        int*   iout = tid ? s_iw : s_ir;
        unsigned used = 0;
        float vals[4];
        #pragma unroll
        for (int k = 0; k < 4; k++) {
            float best = -1e30f; int bi = 0;
            for (int n = 0; n < MEMN; n++) {
                if (!((used >> n) & 1u) && sims[n] > best) { best = sims[n]; bi = n; }
            }
            used |= 1u << bi;
            iout[k] = bi; vals[k] = best;
        }
        float mx = vals[0], ssum = 0.f, e[4];
        #pragma unroll
        for (int k = 0; k < 4; k++) { e[k] = expf(vals[k] - mx); ssum += e[k]; }
        #pragma unroll
        for (int k = 0; k < 4; k++) wout[k] = e[k] / ssum;
    }
    __syncthreads();

    float r = 0.f;
    #pragma unroll
    for (int k = 0; k < 4; k++)
        r += s_wr[k] * g_M[(b*MEMN + s_ir[k])*KSZ + tid];
    g_r[b*KSZ + tid] = r;
    s_rnew[tid] = r;

    #pragma unroll
    for (int k = 0; k < 4; k++)
        g_M[(b*MEMN + s_iw[k])*KSZ + tid] += s_ws[k] * vv;

    if (t == TT - 1) {
        __syncthreads();
        if (wid < 4) {
            const float* wrow = wo + wid*512;
            float p = 0.f;
            for (int j = lane; j < 256; j += 32) p += wrow[j]       * g_hst[b*HH + j];
            for (int j = lane; j < 256; j += 32) p += wrow[256 + j] * s_rnew[j];
            #pragma unroll
            for (int o = 16; o > 0; o >>= 1) p += __shfl_xor_sync(0xffffffffu, p, o);
            if (lane == 0) s_y[wid] = p + wob[wid];
        }
        __syncthreads();
        if (tid < 4 && (b*4 + tid) < out_size) out[b*4 + tid] = s_y[tid];
        if (tid == 0 && out_size >= BB*YY + BB) {
            int am = 0; float bv = s_y[0];
            #pragma unroll
            for (int o = 1; o < 4; o++) if (s_y[o] > bv) { bv = s_y[o]; am = o; }
            out[BB*YY + b] = (float)am;
        }
    }
}

// ---------------- launch ----------------
extern "C" void kernel_launch(void* const* d_in, const int* in_sizes, int n_in,
                              void* d_out, int out_size)
{
    const float* x    = (const float*)d_in[0];
    const float* c1w  = (const float*)d_in[1];
    const float* c1b  = (const float*)d_in[2];
    const float* c2w  = (const float*)d_in[3];
    const float* c2b  = (const float*)d_in[4];
    const float* c3w  = (const float*)d_in[5];
    const float* c3b  = (const float*)d_in[6];
    const float* fc1w = (const float*)d_in[7];
    const float* fc1b = (const float*)d_in[8];
    const float* fc2w = (const float*)d_in[9];
    const float* fc2b = (const float*)d_in[10];
    const float* gamma= (const float*)d_in[11];
    const float* beta = (const float*)d_in[12];
    const float* lwi  = (const float*)d_in[13];
    const float* lwh  = (const float*)d_in[14];
    const float* lb   = (const float*)d_in[15];
    const float* wk   = (const float*)d_in[16];
    const float* wwk  = (const float*)d_in[17];
    const float* wv   = (const float*)d_in[18];
    const float* wo   = (const float*)d_in[19];
    const float* wob  = (const float*)d_in[20];
    const float* mem0 = (const float*)d_in[21];
    float* out = (float*)d_out;

    cudaFuncSetAttribute(k_conv, cudaFuncAttributeMaxDynamicSharedMemorySize,
                         CONV_SMEM_FLOATS * 4);

    float *p_h3, *p_fc1p, *p_fc2p, *p_z, *p_gz, *p_g8, *p_hp, *p_h, *p_wcat, *p_wz, *p_whead;
    cudaGetSymbolAddress((void**)&p_h3,    g_h3);
    cudaGetSymbolAddress((void**)&p_fc1p,  g_fc1p);
    cudaGetSymbolAddress((void**)&p_fc2p,  g_fc2p);
    cudaGetSymbolAddress((void**)&p_z,     g_z);
    cudaGetSymbolAddress((void**)&p_gz,    g_gz);
    cudaGetSymbolAddress((void**)&p_g8,    g_gates8);
    cudaGetSymbolAddress((void**)&p_hp,    g_hpart);
    cudaGetSymbolAddress((void**)&p_h,     g_hst);
    cudaGetSymbolAddress((void**)&p_wcat,  g_Wcat);
    cudaGetSymbolAddress((void**)&p_wz,    g_Wz);
    cudaGetSymbolAddress((void**)&p_whead, g_Whead);

    k_setup<<<(BB*MEMN*KSZ + 255)/256, 256>>>(mem0, lwi, lwh, wk, wwk, wv, out, out_size);

    // encoder
    k_conv<<<NFRM, 256, CONV_SMEM_FLOATS * 4>>>(x, c1w, c1b, c2w, c2b, c3w, c3b);
    // fc1: split-K x2 partials (640 blocks)
    k_gemm_part<<<dim3(4, 80, 2), 256>>>(p_h3, 512, fc1w, 512, nullptr,
                                         p_fc1p, 256, 256, NFRM*256, 0);
    // fc2: split-K x2 partials, A = relu(fc1p0+fc1p1+fc1b) fused (320 blocks)
    k_gemm_part<<<dim3(2, 80, 2), 256>>>(nullptr, 0, fc2w, 256, fc1b,
                                         p_fc2p, 128, 128, NFRM*DD, 2);
    k_ctxnorm<<<BB, 128>>>(fc2b, gamma, beta);
    // Gz = z @ Wz^T + lstm_b for all (b,t) (1280 blocks)
    k_gemm<<<dim3(16, 80), 256>>>(p_z, 128, p_wz, 128, lb, p_gz, 1024, 128, 0);

    for (int t = 0; t < TT; t++) {
        // gates: [r|h] @ Wcat^T, split-K x8 (512 blocks)
        k_gemm_part<<<dim3(16, 4, GSPL), 256>>>(nullptr, 0, p_wcat, 512, nullptr,
                                                p_g8, 1024, 64, BB*1024, 1);
        k_lstm<<<64, 256>>>(t);
        // heads: h @ Whead^T, split-K x4 (192 blocks)
        k_gemm_part<<<dim3(12, 4, 4), 256>>>(p_h, 256, p_whead, 256, nullptr,
                                             p_hp, 768, 64, BB*768, 0);
        k_mem<<<BB, 256>>>(t, wo, wob, out, out_size);
    }
}

// round 6
// speedup vs baseline: 1.0628x; 1.0628x over previous
#include <cuda_runtime.h>
#include <math.h>

#define BB 256
#define TT 20
#define DD 128
#define HH 256
#define KSZ 256
#define MEMN 20
#define YY 4
#define EPSF 1e-8f
#define NFRM (BB*TT)

// ---------------- device scratch ----------------
__device__ float g_h3[NFRM*512];
__device__ float g_fc1[NFRM*256];
__device__ float g_fc2p[2*NFRM*DD];     // fc2 split-K partials
__device__ float g_z[NFRM*DD];
__device__ float g_gz[NFRM*1024];       // precomputed z@Wz^T + lstm_b
__device__ float g_gates4[4*BB*1024];   // gates split-K partials
__device__ float g_hpart[4*BB*768];     // heads split-K partials
__device__ float g_hst[BB*HH];
__device__ float g_cst[BB*HH];
__device__ float g_r[BB*KSZ];
__device__ float g_M[BB*MEMN*KSZ];
__device__ float g_Wcat[1024*512];      // [Wr | Wh]
__device__ float g_Wz[1024*128];
__device__ float g_Whead[768*256];

__device__ __forceinline__ float sigmf(float x){ return 1.f/(1.f+expf(-x)); }

// ---------------- fused conv encoder: one frame per block ----------------
#define S_IN 0
#define S_H1 1156
#define S_H2 12676
#define CONV_SMEM_FLOATS 16516

__global__ void __launch_bounds__(256, 3) k_conv(
    const float* __restrict__ x,
    const float* __restrict__ w1, const float* __restrict__ b1,
    const float* __restrict__ w2, const float* __restrict__ b2,
    const float* __restrict__ w3, const float* __restrict__ b3)
{
    extern __shared__ float sm[];
    float* s_in = sm + S_IN;
    float* s_h1 = sm + S_H1;
    float* s_h2 = sm + S_H2;
    const int f   = blockIdx.x;
    const int tid = threadIdx.x;

    for (int i = tid; i < CONV_SMEM_FLOATS; i += 256) sm[i] = 0.f;
    __syncthreads();
    for (int i = tid; i < 1024; i += 256) {
        int iy = i >> 5, ix = i & 31;
        s_in[(iy+1)*34 + ix + 1] = x[f*1024 + i];
    }
    __syncthreads();

    // ---- conv1 ----
    for (int p = tid; p < 32*16; p += 256) {
        int oc = p >> 4, oy = p & 15;
        float bias = __ldg(b1 + oc);
        float acc[16];
        #pragma unroll
        for (int ox = 0; ox < 16; ox++) acc[ox] = bias;
        #pragma unroll
        for (int kh = 0; kh < 4; kh++) {
            const float* row = s_in + (2*oy+kh)*34;
            const float4 w = __ldg((const float4*)(w1 + oc*16 + kh*4));
            #pragma unroll
            for (int ox = 0; ox < 16; ox++) {
                acc[ox] += row[2*ox]*w.x + row[2*ox+1]*w.y
                         + row[2*ox+2]*w.z + row[2*ox+3]*w.w;
            }
        }
        float* dst = s_h1 + oc*360 + (oy+1)*20 + 1;
        #pragma unroll
        for (int ox = 0; ox < 16; ox++) dst[ox] = fmaxf(acc[ox], 0.f);
    }
    __syncthreads();

    // ---- conv2: 128 threads (2 oc x 8 ox per thread, activation reuse) ----
    if (tid < 128) {
        int ocp = tid >> 3;
        int oy  = tid & 7;
        int oc0 = ocp*2, oc1 = oc0 + 1;
        float bv0 = __ldg(b2 + oc0), bv1 = __ldg(b2 + oc1);
        float acc0[8] = {bv0,bv0,bv0,bv0,bv0,bv0,bv0,bv0};
        float acc1[8] = {bv1,bv1,bv1,bv1,bv1,bv1,bv1,bv1};
        for (int ic = 0; ic < 32; ic++) {
            const float* chan = s_h1 + ic*360;
            #pragma unroll
            for (int kh = 0; kh < 4; kh++) {
                const float* row = chan + (2*oy+kh)*20;
                float4 r0 = *(const float4*)(row);
                float4 r1 = *(const float4*)(row+4);
                float4 r2 = *(const float4*)(row+8);
                float4 r3 = *(const float4*)(row+12);
                float2 r4 = *(const float2*)(row+16);
                float rr[18] = {r0.x,r0.y,r0.z,r0.w, r1.x,r1.y,r1.z,r1.w,
                                r2.x,r2.y,r2.z,r2.w, r3.x,r3.y,r3.z,r3.w,
                                r4.x,r4.y};
                const float4 wa = __ldg((const float4*)(w2 + oc0*512 + ic*16 + kh*4));
                const float4 wb = __ldg((const float4*)(w2 + oc1*512 + ic*16 + kh*4));
                #pragma unroll
                for (int ox = 0; ox < 8; ox++) {
                    acc0[ox] += rr[2*ox]*wa.x + rr[2*ox+1]*wa.y
                              + rr[2*ox+2]*wa.z + rr[2*ox+3]*wa.w;
                    acc1[ox] += rr[2*ox]*wb.x + rr[2*ox+1]*wb.y
                              + rr[2*ox+2]*wb.z + rr[2*ox+3]*wb.w;
                }
            }
        }
        float* d0 = s_h2 + oc0*120 + (oy+1)*12 + 1;
        float* d1 = s_h2 + oc1*120 + (oy+1)*12 + 1;
        #pragma unroll
        for (int ox = 0; ox < 8; ox++) {
            d0[ox] = fmaxf(acc0[ox], 0.f);
            d1[ox] = fmaxf(acc1[ox], 0.f);
        }
    }
    __syncthreads();

    // ---- conv3 ----
    {
        int oc = tid >> 3, oy = (tid >> 1) & 3, q = tid & 1;
        float bias = __ldg(b3 + oc);
        float acc0 = bias, acc1 = bias;
        for (int ic = 0; ic < 32; ic++) {
            const float* chan = s_h2 + ic*120;
            #pragma unroll
            for (int kh = 0; kh < 4; kh++) {
                const float* row = chan + (2*oy+kh)*12 + 4*q;
                float4 a = *(const float4*)(row);
                float4 b = *(const float4*)(row+4);
                const float4 w = __ldg((const float4*)(w3 + oc*512 + ic*16 + kh*4));
                acc0 += a.x*w.x + a.y*w.y + a.z*w.z + a.w*w.w;
                acc1 += a.z*w.x + a.w*w.y + b.x*w.z + b.y*w.w;
            }
        }
        int base = f*512 + oc*16 + oy*4 + 2*q;
        g_h3[base]   = fmaxf(acc0, 0.f);
        g_h3[base+1] = fmaxf(acc1, 0.f);
    }
}

// ---------------- 3xTF32 tensor-core GEMM: C = ep(A @ W^T [+ bias]) ----------------
// Block tile 64(M) x 128(N), BK=32, 256 threads = 8 warps (2x4 of 32x32).
// mode 0: A plain [*,lda]. mode 1: A row b = [r(b,:) | h(b,:)] (512 cols).
// ep 0: partial (C + z*partStride, no bias). ep 1: +bias. ep 2: +bias, relu.
__device__ __forceinline__ void mma8(float* c, const unsigned* a, const unsigned* b)
{
    asm volatile(
        "mma.sync.aligned.m16n8k8.row.col.f32.tf32.tf32.f32 "
        "{%0,%1,%2,%3},{%4,%5,%6,%7},{%8,%9},{%0,%1,%2,%3};"
        : "+f"(c[0]), "+f"(c[1]), "+f"(c[2]), "+f"(c[3])
        : "r"(a[0]), "r"(a[1]), "r"(a[2]), "r"(a[3]), "r"(b[0]), "r"(b[1]));
}
__device__ __forceinline__ void split2(float x, unsigned& hi, unsigned& lo)
{
    unsigned h = __float_as_uint(x) & 0xffffe000u;   // exact tf32 (truncated)
    hi = h;
    lo = __float_as_uint(x - __uint_as_float(h));    // residual; HW reads top tf32 bits
}

__global__ void __launch_bounds__(256) k_tc(
    const float* __restrict__ A, int lda,
    const float* __restrict__ W, int ldw,
    const float* __restrict__ bias,
    float* __restrict__ C, int ldc,
    int Ksplit, int partStride, int mode, int ep)
{
    __shared__ float sA[32][72];     // [k][m], stride 72 ≡ 8 (mod 32)
    __shared__ float sW[32][136];    // [k][n], stride 136 ≡ 8 (mod 32)

    const int tid = threadIdx.x;
    const int warpid = tid >> 5, lane = tid & 31;
    const int g = lane >> 2, tig = lane & 3;
    const int wm = warpid >> 2, wn = warpid & 3;
    const int mtile = blockIdx.y, ntile = blockIdx.x, z = blockIdx.z;
    const int kStart = z * Ksplit;

    const float* Ab; int abase;
    int ldae;
    if (mode == 1) {
        if (kStart < KSZ) { Ab = g_r;  abase = kStart; }
        else              { Ab = g_hst; abase = kStart - KSZ; }
        ldae = 256;
    } else { Ab = A; abase = kStart; ldae = lda; }
    float* Cp = C + z * partStride;

    // A: 2 float4 per thread; W: 4 float4 per thread
    const int aidx0 = tid,        aidx1 = tid + 256;
    const int arow0 = aidx0 & 63, akq0 = aidx0 >> 6;
    const int arow1 = aidx1 & 63, akq1 = aidx1 >> 6;
    const float* Abase0 = Ab + (mtile*64 + arow0)*ldae + abase + akq0*4;
    const float* Abase1 = Ab + (mtile*64 + arow1)*ldae + abase + akq1*4;

    float acc[2][4][4];
    #pragma unroll
    for (int mi = 0; mi < 2; mi++)
        #pragma unroll
        for (int ni = 0; ni < 4; ni++)
            #pragma unroll
            for (int q = 0; q < 4; q++) acc[mi][ni][q] = 0.f;

    const int nkc = Ksplit >> 5;
    float4 pa0 = *(const float4*)(Abase0);
    float4 pa1 = *(const float4*)(Abase1);
    float4 pw[4];
    #pragma unroll
    for (int q = 0; q < 4; q++) {
        int idx = tid + q*256;
        int n = idx & 127, kq = idx >> 7;
        pw[q] = *(const float4*)(W + (ntile*128 + n)*ldw + kStart + kq*4);
    }

    for (int kt = 0; kt < nkc; kt++) {
        // stage chunk kt
        sA[akq0*4+0][arow0] = pa0.x; sA[akq0*4+1][arow0] = pa0.y;
        sA[akq0*4+2][arow0] = pa0.z; sA[akq0*4+3][arow0] = pa0.w;
        sA[akq1*4+0][arow1] = pa1.x; sA[akq1*4+1][arow1] = pa1.y;
        sA[akq1*4+2][arow1] = pa1.z; sA[akq1*4+3][arow1] = pa1.w;
        #pragma unroll
        for (int q = 0; q < 4; q++) {
            int idx = tid + q*256;
            int n = idx & 127, kq = idx >> 7;
            sW[kq*4+0][n] = pw[q].x; sW[kq*4+1][n] = pw[q].y;
            sW[kq*4+2][n] = pw[q].z; sW[kq*4+3][n] = pw[q].w;
        }
        __syncthreads();

        if (kt + 1 < nkc) {
            int kb = (kt+1) << 5;
            pa0 = *(const float4*)(Abase0 + kb);
            pa1 = *(const float4*)(Abase1 + kb);
            #pragma unroll
            for (int q = 0; q < 4; q++) {
                int idx = tid + q*256;
                int n = idx & 127, kq = idx >> 7;
                pw[q] = *(const float4*)(W + (ntile*128 + n)*ldw + kStart + kb + kq*4);
            }
        }

        #pragma unroll
        for (int kk = 0; kk < 4; kk++) {
            const int k0 = kk*8 + tig, k1 = k0 + 4;
            unsigned ahi[2][4], alo[2][4], bhi[4][2], blo[4][2];
            #pragma unroll
            for (int mi = 0; mi < 2; mi++) {
                int r0 = wm*32 + mi*16 + g;
                split2(sA[k0][r0],    ahi[mi][0], alo[mi][0]);
                split2(sA[k0][r0+8],  ahi[mi][1], alo[mi][1]);
                split2(sA[k1][r0],    ahi[mi][2], alo[mi][2]);
                split2(sA[k1][r0+8],  ahi[mi][3], alo[mi][3]);
            }
            #pragma unroll
            for (int ni = 0; ni < 4; ni++) {
                int c0 = wn*32 + ni*8 + g;
                split2(sW[k0][c0], bhi[ni][0], blo[ni][0]);
                split2(sW[k1][c0], bhi[ni][1], blo[ni][1]);
            }
            #pragma unroll
            for (int mi = 0; mi < 2; mi++)
                #pragma unroll
                for (int ni = 0; ni < 4; ni++) {
                    mma8(acc[mi][ni], ahi[mi], bhi[ni]);
                    mma8(acc[mi][ni], alo[mi], bhi[ni]);
                    mma8(acc[mi][ni], ahi[mi], blo[ni]);
                }
        }
        __syncthreads();
    }

    // epilogue
    #pragma unroll
    for (int mi = 0; mi < 2; mi++) {
        #pragma unroll
        for (int ni = 0; ni < 4; ni++) {
            int row0 = mtile*64 + wm*32 + mi*16 + g;
            int col0 = ntile*128 + wn*32 + ni*8 + 2*tig;
            float v0 = acc[mi][ni][0], v1 = acc[mi][ni][1];
            float v2 = acc[mi][ni][2], v3 = acc[mi][ni][3];
            if (ep >= 1) {
                float b0 = bias[col0], b1 = bias[col0+1];
                v0 += b0; v1 += b1; v2 += b0; v3 += b1;
            }
            if (ep == 2) {
                v0 = fmaxf(v0, 0.f); v1 = fmaxf(v1, 0.f);
                v2 = fmaxf(v2, 0.f); v3 = fmaxf(v3, 0.f);
            }
            float* p = Cp + row0*ldc + col0;
            p[0] = v0; p[1] = v1;
            p[8*ldc] = v2; p[8*ldc + 1] = v3;
        }
    }
}

// ---------------- context norm over time, fused fc2 combine + bias + relu ------------
__global__ void k_ctxnorm(const float* __restrict__ fc2b,
                          const float* __restrict__ gamma, const float* __restrict__ beta)
{
    int b = blockIdx.x, d = threadIdx.x;
    float bias = fc2b[d];
    float v[TT];
    float s = 0.f, s2 = 0.f;
    #pragma unroll
    for (int t = 0; t < TT; t++) {
        int idx = (b*TT+t)*DD + d;
        v[t] = fmaxf(g_fc2p[idx] + g_fc2p[NFRM*DD + idx] + bias, 0.f);
        s += v[t]; s2 += v[t]*v[t];
    }
    float mu  = s / TT;
    float var = (s2 - TT*mu*mu) / (TT - 1);
    float inv = 1.f / sqrtf(var + EPSF);
    float ga = gamma[d], be = beta[d];
    #pragma unroll
    for (int t = 0; t < TT; t++)
        g_z[(b*TT+t)*DD + d] = (v[t] - mu)*inv*ga + be;
}

// ---------------- setup ----------------
__global__ void k_setup(const float* __restrict__ mem0,
                        const float* __restrict__ wi, const float* __restrict__ wh,
                        const float* __restrict__ wk, const float* __restrict__ wwk,
                        const float* __restrict__ wv,
                        float* __restrict__ out, int out_size)
{
    int i = blockIdx.x*256 + threadIdx.x;
    if (i < BB*MEMN*KSZ) g_M[i] = mem0[i % (MEMN*KSZ)];
    if (i < 1024*512) {
        int j = i >> 9, c = i & 511;
        g_Wcat[i] = (c < 256) ? wi[j*384 + 128 + c] : wh[j*256 + (c-256)];
    }
    if (i < 1024*128) {
        int j = i >> 7, c = i & 127;
        g_Wz[i] = wi[j*384 + c];
    }
    if (i < 768*256) {
        int n = i >> 8;
        g_Whead[i] = (n < 256) ? wk[i] : ((n < 512) ? wwk[i - 256*256] : wv[i - 512*256]);
    }
    if (i < BB*HH) { g_hst[i] = 0.f; g_cst[i] = 0.f; }
    if (i < BB*KSZ) g_r[i] = 0.f;
    if (i < out_size) out[i] = 0.f;
}

// ---------------- per-step: LSTM update (sums gz + 4 gate partials, float4) ----------
__global__ void k_lstm(int t)
{
    int idx = blockIdx.x*256 + threadIdx.x;   // BB*64 threads, 4 j's each
    int b = idx >> 6, j = (idx & 63) << 2;
    const float* gz = g_gz + (b*TT + t)*1024;
    float4 g[4];
    #pragma unroll
    for (int gt = 0; gt < 4; gt++) g[gt] = *(const float4*)(gz + gt*256 + j);
    #pragma unroll
    for (int z = 0; z < 4; z++) {
        const float* gp = g_gates4 + z*(BB*1024) + b*1024;
        #pragma unroll
        for (int gt = 0; gt < 4; gt++) {
            float4 p = *(const float4*)(gp + gt*256 + j);
            g[gt].x += p.x; g[gt].y += p.y; g[gt].z += p.z; g[gt].w += p.w;
        }
    }
    float4 c = *(const float4*)(g_cst + b*HH + j);
    float4 cn, hn;
    cn.x = sigmf(g[1].x)*c.x + sigmf(g[0].x)*tanhf(g[2].x);
    cn.y = sigmf(g[1].y)*c.y + sigmf(g[0].y)*tanhf(g[2].y);
    cn.z = sigmf(g[1].z)*c.z + sigmf(g[0].z)*tanhf(g[2].z);
    cn.w = sigmf(g[1].w)*c.w + sigmf(g[0].w)*tanhf(g[2].w);
    hn.x = sigmf(g[3].x)*tanhf(cn.x);
    hn.y = sigmf(g[3].y)*tanhf(cn.y);
    hn.z = sigmf(g[3].z)*tanhf(cn.z);
    hn.w = sigmf(g[3].w)*tanhf(cn.w);
    *(float4*)(g_cst + b*HH + j) = cn;
    *(float4*)(g_hst + b*HH + j) = hn;
}

// ---------------- per-step: memory read/write + (last step) output ----------------
__global__ void __launch_bounds__(256) k_mem(int t, const float* __restrict__ wo,
                                             const float* __restrict__ wob,
                                             float* __restrict__ out, int out_size)
{
    __shared__ float s_kr[256], s_kw[256], s_rnew[256];
    __shared__ float s_simr[MEMN], s_simw[MEMN];
    __shared__ float s_wr[4], s_ws[4];
    __shared__ int   s_ir[4], s_iw[4];
    __shared__ float s_red[16];
    __shared__ float s_nrm[2];
    __shared__ float s_y[4];

    int b = blockIdx.x, tid = threadIdx.x;
    int lane = tid & 31, wid = tid >> 5;

    float kr = 0.f, kw = 0.f, vvs = 0.f;
    #pragma unroll
    for (int z = 0; z < 4; z++) {
        const float* hp = g_hpart + z*(BB*768) + b*768;
        kr  += hp[tid];
        kw  += hp[256 + tid];
        vvs += hp[512 + tid];
    }
    float vv = tanhf(vvs);
    s_kr[tid] = kr;
    s_kw[tid] = kw;

    float pr = kr*kr, pw = kw*kw;
    #pragma unroll
    for (int o = 16; o > 0; o >>= 1) {
        pr += __shfl_xor_sync(0xffffffffu, pr, o);
        pw += __shfl_xor_sync(0xffffffffu, pw, o);
    }
    if (lane == 0) { s_red[wid] = pr; s_red[8 + wid] = pw; }
    __syncthreads();
    if (tid == 0) {
        float sr = 0.f, sw = 0.f;
        #pragma unroll
        for (int w = 0; w < 8; w++) { sr += s_red[w]; sw += s_red[8 + w]; }
        s_nrm[0] = 1.f / (sqrtf(sr) + EPSF);
        s_nrm[1] = 1.f / (sqrtf(sw) + EPSF);
    }
    __syncthreads();

    for (int n = wid; n < MEMN; n += 8) {
        const float* Mr = g_M + (b*MEMN + n)*KSZ;
        float dr = 0.f, dw = 0.f, nn = 0.f;
        #pragma unroll
        for (int d0 = 0; d0 < KSZ; d0 += 32) {
            float m = Mr[d0 + lane];
            dr += s_kr[d0 + lane]*m;
            dw += s_kw[d0 + lane]*m;
            nn += m*m;
        }
        #pragma unroll
        for (int o = 16; o > 0; o >>= 1) {
            dr += __shfl_xor_sync(0xffffffffu, dr, o);
            dw += __shfl_xor_sync(0xffffffffu, dw, o);
            nn += __shfl_xor_sync(0xffffffffu, nn, o);
        }
        if (lane == 0) {
            float mi = 1.f / (sqrtf(nn) + EPSF);
            s_simr[n] = dr * s_nrm[0] * mi;
            s_simw[n] = dw * s_nrm[1] * mi;
        }
    }
    __syncthreads();

    if (tid < 2) {
        const float* sims = tid ? s_simw : s_simr;
        float* wout = tid ? s_ws : s_wr;
        int*   iout = tid ? s_iw : s_ir;
        unsigned used = 0;
        float vals[4];
        #pragma unroll
        for (int k = 0; k < 4; k++) {
            float best = -1e30f; int bi = 0;
            for (int n = 0; n < MEMN; n++) {
                if (!((used >> n) & 1u) && sims[n] > best) { best = sims[n]; bi = n; }
            }
            used |= 1u << bi;
            iout[k] = bi; vals[k] = best;
        }
        float mx = vals[0], ssum = 0.f, e[4];
        #pragma unroll
        for (int k = 0; k < 4; k++) { e[k] = expf(vals[k] - mx); ssum += e[k]; }
        #pragma unroll
        for (int k = 0; k < 4; k++) wout[k] = e[k] / ssum;
    }
    __syncthreads();

    float r = 0.f;
    #pragma unroll
    for (int k = 0; k < 4; k++)
        r += s_wr[k] * g_M[(b*MEMN + s_ir[k])*KSZ + tid];
    g_r[b*KSZ + tid] = r;
    s_rnew[tid] = r;

    #pragma unroll
    for (int k = 0; k < 4; k++)
        g_M[(b*MEMN + s_iw[k])*KSZ + tid] += s_ws[k] * vv;

    if (t == TT - 1) {
        __syncthreads();
        if (wid < 4) {
            const float* wrow = wo + wid*512;
            float p = 0.f;
            for (int j = lane; j < 256; j += 32) p += wrow[j]       * g_hst[b*HH + j];
            for (int j = lane; j < 256; j += 32) p += wrow[256 + j] * s_rnew[j];
            #pragma unroll
            for (int o = 16; o > 0; o >>= 1) p += __shfl_xor_sync(0xffffffffu, p, o);
            if (lane == 0) s_y[wid] = p + wob[wid];
        }
        __syncthreads();
        if (tid < 4 && (b*4 + tid) < out_size) out[b*4 + tid] = s_y[tid];
        if (tid == 0 && out_size >= BB*YY + BB) {
            int am = 0; float bv = s_y[0];
            #pragma unroll
            for (int o = 1; o < 4; o++) if (s_y[o] > bv) { bv = s_y[o]; am = o; }
            out[BB*YY + b] = (float)am;
        }
    }
}

// ---------------- launch ----------------
extern "C" void kernel_launch(void* const* d_in, const int* in_sizes, int n_in,
                              void* d_out, int out_size)
{
    const float* x    = (const float*)d_in[0];
    const float* c1w  = (const float*)d_in[1];
    const float* c1b  = (const float*)d_in[2];
    const float* c2w  = (const float*)d_in[3];
    const float* c2b  = (const float*)d_in[4];
    const float* c3w  = (const float*)d_in[5];
    const float* c3b  = (const float*)d_in[6];
    const float* fc1w = (const float*)d_in[7];
    const float* fc1b = (const float*)d_in[8];
    const float* fc2w = (const float*)d_in[9];
    const float* fc2b = (const float*)d_in[10];
    const float* gamma= (const float*)d_in[11];
    const float* beta = (const float*)d_in[12];
    const float* lwi  = (const float*)d_in[13];
    const float* lwh  = (const float*)d_in[14];
    const float* lb   = (const float*)d_in[15];
    const float* wk   = (const float*)d_in[16];
    const float* wwk  = (const float*)d_in[17];
    const float* wv   = (const float*)d_in[18];
    const float* wo   = (const float*)d_in[19];
    const float* wob  = (const float*)d_in[20];
    const float* mem0 = (const float*)d_in[21];
    float* out = (float*)d_out;

    cudaFuncSetAttribute(k_conv, cudaFuncAttributeMaxDynamicSharedMemorySize,
                         CONV_SMEM_FLOATS * 4);

    float *p_h3, *p_fc1, *p_fc2p, *p_z, *p_gz, *p_g4, *p_hp, *p_h, *p_wcat, *p_wz, *p_whead;
    cudaGetSymbolAddress((void**)&p_h3,    g_h3);
    cudaGetSymbolAddress((void**)&p_fc1,   g_fc1);
    cudaGetSymbolAddress((void**)&p_fc2p,  g_fc2p);
    cudaGetSymbolAddress((void**)&p_z,     g_z);
    cudaGetSymbolAddress((void**)&p_gz,    g_gz);
    cudaGetSymbolAddress((void**)&p_g4,    g_gates4);
    cudaGetSymbolAddress((void**)&p_hp,    g_hpart);
    cudaGetSymbolAddress((void**)&p_h,     g_hst);
    cudaGetSymbolAddress((void**)&p_wcat,  g_Wcat);
    cudaGetSymbolAddress((void**)&p_wz,    g_Wz);
    cudaGetSymbolAddress((void**)&p_whead, g_Whead);

    k_setup<<<(BB*MEMN*KSZ + 255)/256, 256>>>(mem0, lwi, lwh, wk, wwk, wv, out, out_size);

    // encoder
    k_conv<<<NFRM, 256, CONV_SMEM_FLOATS * 4>>>(x, c1w, c1b, c2w, c2b, c3w, c3b);
    // fc1: [5120,512]@[256,512]^T + b -> relu (tensor cores, 160 blocks)
    k_tc<<<dim3(2, 80, 1), 256>>>(p_h3, 512, fc1w, 512, fc1b, p_fc1, 256, 512, 0, 0, 2);
    // fc2: split-K x2 partials (160 blocks); combine in ctxnorm
    k_tc<<<dim3(1, 80, 2), 256>>>(p_fc1, 256, fc2w, 256, nullptr, p_fc2p, 128,
                                  128, NFRM*DD, 0, 0);
    k_ctxnorm<<<BB, 128>>>(fc2b, gamma, beta);
    // Gz = z @ Wz^T + lstm_b for all (b,t) (640 blocks)
    k_tc<<<dim3(8, 80, 1), 256>>>(p_z, 128, p_wz, 128, lb, p_gz, 1024, 128, 0, 0, 1);

    for (int t = 0; t < TT; t++) {
        // gates: [r|h] @ Wcat^T, split-K x4 (128 blocks)
        k_tc<<<dim3(8, 4, 4), 256>>>(nullptr, 0, p_wcat, 512, nullptr, p_g4, 1024,
                                     128, BB*1024, 1, 0);
        k_lstm<<<64, 256>>>(t);
        // heads: h @ Whead^T, split-K x4 (96 blocks)
        k_tc<<<dim3(6, 4, 4), 256>>>(p_h, 256, p_whead, 256, nullptr, p_hp, 768,
                                     64, BB*768, 0, 0);
        k_mem<<<BB, 256>>>(t, wo, wob, out, out_size);
    }
}

// round 7
// speedup vs baseline: 1.4598x; 1.3735x over previous
#include <cuda_runtime.h>
#include <math.h>

#define BB 256
#define TT 20
#define DD 128
#define HH 256
#define KSZ 256
#define MEMN 20
#define YY 4
#define EPSF 1e-8f
#define NFRM (BB*TT)

// ---------------- device scratch ----------------
__device__ float g_h3[NFRM*512];
__device__ float g_fc1[NFRM*256];
__device__ float g_fc2p[2*NFRM*DD];     // fc2 split-K partials
__device__ float g_z[NFRM*DD];
__device__ float g_gz[NFRM*1024];       // precomputed z@Wz^T + lstm_b
__device__ float g_gates4[4*BB*1024];   // gates split-K partials
__device__ float g_hpart[4*BB*768];     // heads split-K partials
__device__ float g_hst[BB*HH];
__device__ float g_cst[BB*HH];
__device__ float g_r[BB*KSZ];
__device__ float g_M[BB*MEMN*KSZ];
__device__ float g_Wcat[1024*512];      // [Wr | Wh]
__device__ float g_Wz[1024*128];
__device__ float g_Whead[768*256];
__device__ float g_w2r[16384];          // conv2 weights, mma-fragment order
__device__ float g_w3r[16384];          // conv3 weights, mma-fragment order

__device__ __forceinline__ float sigmf(float x){ return 1.f/(1.f+expf(-x)); }

// ---------------- tf32 mma helpers ----------------
__device__ __forceinline__ void mma8(float* c, const unsigned* a, const unsigned* b)
{
    asm volatile(
        "mma.sync.aligned.m16n8k8.row.col.f32.tf32.tf32.f32 "
        "{%0,%1,%2,%3},{%4,%5,%6,%7},{%8,%9},{%0,%1,%2,%3};"
        : "+f"(c[0]), "+f"(c[1]), "+f"(c[2]), "+f"(c[3])
        : "r"(a[0]), "r"(a[1]), "r"(a[2]), "r"(a[3]), "r"(b[0]), "r"(b[1]));
}
__device__ __forceinline__ void split2(float x, unsigned& hi, unsigned& lo)
{
    unsigned h = __float_as_uint(x) & 0xffffe000u;   // exact tf32 (truncated)
    hi = h;
    lo = __float_as_uint(x - __uint_as_float(h));
}

// ---------------- fused conv encoder (tensor-core conv2/conv3) ----------------
// smem (floats): s_in 34x34 = 1156 | s_h1 channel-last 18x18 cells x stride 37
// = 11988 | s_h2 channel-last 10x10 cells x stride 37 = 3700 | s_c3 32x33 = 1056
#define S_H1 1156
#define S_H2 13144
#define S_C3 16844
#define CONVF_SMEM_FLOATS 17900

__global__ void __launch_bounds__(256, 2) k_convf(
    const float* __restrict__ x,
    const float* __restrict__ w1, const float* __restrict__ b1,
    const float* __restrict__ w2r, const float* __restrict__ b2,
    const float* __restrict__ w3r, const float* __restrict__ b3)
{
    extern __shared__ float sm[];
    float* s_in = sm;
    float* s_h1 = sm + S_H1;
    float* s_h2 = sm + S_H2;
    float* s_c3 = sm + S_C3;
    const int f = blockIdx.x, tid = threadIdx.x;
    const int lane = tid & 31, warpid = tid >> 5;
    const int g = lane >> 2, tig = lane & 3;

    for (int i = tid; i < S_C3; i += 256) sm[i] = 0.f;
    __syncthreads();
    for (int i = tid; i < 1024; i += 256) {
        int iy = i >> 5, ix = i & 31;
        s_in[(iy+1)*34 + ix + 1] = x[f*1024 + i];
    }
    __syncthreads();

    // ---- conv1 (FFMA): 1->32ch, 32x32 -> 16x16, write channel-last ----
    for (int p = tid; p < 512; p += 256) {
        int oc = p >> 4, oy = p & 15;
        float bias = __ldg(b1 + oc);
        float acc[16];
        #pragma unroll
        for (int ox = 0; ox < 16; ox++) acc[ox] = bias;
        #pragma unroll
        for (int kh = 0; kh < 4; kh++) {
            const float* row = s_in + (2*oy+kh)*34;
            const float4 w = __ldg((const float4*)(w1 + oc*16 + kh*4));
            #pragma unroll
            for (int ox = 0; ox < 16; ox++) {
                acc[ox] += row[2*ox]*w.x + row[2*ox+1]*w.y
                         + row[2*ox+2]*w.z + row[2*ox+3]*w.w;
            }
        }
        int cellbase = (oy+1)*18 + 1;
        #pragma unroll
        for (int ox = 0; ox < 16; ox++)
            s_h1[(cellbase + ox)*37 + oc] = fmaxf(acc[ox], 0.f);
    }
    __syncthreads();

    // ---- conv2 (tf32 mma): M=64 positions, N=32 oc, K=512 (ic,kh,kw) ----
    {
        const int wm = warpid & 3, wn = warpid >> 2;      // 4 m-tiles x 2 n16
        float acc[2][4] = {{0.f,0.f,0.f,0.f},{0.f,0.f,0.f,0.f}};
        int pA = wm*16 + g, pB = pA + 8;
        int oyA = pA >> 3, oxA = pA & 7;
        int oyB = pB >> 3, oxB = pB & 7;
        #pragma unroll 1
        for (int khw = 0; khw < 16; khw++) {
            int kh = khw >> 2, kw = khw & 3;
            const float* hA = s_h1 + ((2*oyA + kh)*18 + 2*oxA + kw)*37;
            const float* hB = s_h1 + ((2*oyB + kh)*18 + 2*oxB + kw)*37;
            #pragma unroll
            for (int ick = 0; ick < 4; ick++) {
                int ic0 = ick*8;
                unsigned ahi[4], alo[4];
                split2(hA[ic0+tig],   ahi[0], alo[0]);
                split2(hB[ic0+tig],   ahi[1], alo[1]);
                split2(hA[ic0+tig+4], ahi[2], alo[2]);
                split2(hB[ic0+tig+4], ahi[3], alo[3]);
                int idx128 = (khw*4 + ick)*2;
                #pragma unroll
                for (int ni = 0; ni < 2; ni++) {
                    int n8i = wn*2 + ni;
                    unsigned bhi[2], blo[2];
                    float b0 = __ldg(w2r + ((idx128+0)*4 + n8i)*32 + lane);
                    float b1v= __ldg(w2r + ((idx128+1)*4 + n8i)*32 + lane);
                    split2(b0,  bhi[0], blo[0]);
                    split2(b1v, bhi[1], blo[1]);
                    mma8(acc[ni], ahi, bhi);
                    mma8(acc[ni], alo, bhi);
                    mma8(acc[ni], ahi, blo);
                }
            }
        }
        // epilogue: bias + relu -> s_h2 channel-last (with pad margin)
        int cellA = (oyA+1)*10 + oxA + 1;
        int cellB = (oyB+1)*10 + oxB + 1;
        #pragma unroll
        for (int ni = 0; ni < 2; ni++) {
            int col0 = wn*16 + ni*8 + 2*tig;
            float bb0 = __ldg(b2 + col0), bb1 = __ldg(b2 + col0 + 1);
            s_h2[cellA*37 + col0]     = fmaxf(acc[ni][0] + bb0, 0.f);
            s_h2[cellA*37 + col0 + 1] = fmaxf(acc[ni][1] + bb1, 0.f);
            s_h2[cellB*37 + col0]     = fmaxf(acc[ni][2] + bb0, 0.f);
            s_h2[cellB*37 + col0 + 1] = fmaxf(acc[ni][3] + bb1, 0.f);
        }
    }
    __syncthreads();

    // ---- conv3 (tf32 mma): M=16, N=32, K=512; 2-way K-split across warps ----
    {
        const int n8i = warpid & 3, khalf = warpid >> 2;
        float acc[4] = {0.f, 0.f, 0.f, 0.f};
        int pA = g, pB = g + 8;
        int oyA = pA >> 2, oxA = pA & 3;
        int oyB = pB >> 2, oxB = pB & 3;
        #pragma unroll 1
        for (int kk = 0; kk < 8; kk++) {
            int khw = khalf*8 + kk;
            int kh = khw >> 2, kw = khw & 3;
            const float* hA = s_h2 + ((2*oyA + kh)*10 + 2*oxA + kw)*37;
            const float* hB = s_h2 + ((2*oyB + kh)*10 + 2*oxB + kw)*37;
            #pragma unroll
            for (int ick = 0; ick < 4; ick++) {
                int ic0 = ick*8;
                unsigned ahi[4], alo[4];
                split2(hA[ic0+tig],   ahi[0], alo[0]);
                split2(hB[ic0+tig],   ahi[1], alo[1]);
                split2(hA[ic0+tig+4], ahi[2], alo[2]);
                split2(hB[ic0+tig+4], ahi[3], alo[3]);
                int idx128 = (khw*4 + ick)*2;
                unsigned bhi[2], blo[2];
                float b0 = __ldg(w3r + ((idx128+0)*4 + n8i)*32 + lane);
                float b1v= __ldg(w3r + ((idx128+1)*4 + n8i)*32 + lane);
                split2(b0,  bhi[0], blo[0]);
                split2(b1v, bhi[1], blo[1]);
                mma8(acc, ahi, bhi);
                mma8(acc, alo, bhi);
                mma8(acc, ahi, blo);
            }
        }
        int col0 = n8i*8 + 2*tig;
        s_c3[(khalf*16 + g)*33 + col0]       = acc[0];
        s_c3[(khalf*16 + g)*33 + col0 + 1]   = acc[1];
        s_c3[(khalf*16 + g+8)*33 + col0]     = acc[2];
        s_c3[(khalf*16 + g+8)*33 + col0 + 1] = acc[3];
    }
    __syncthreads();
    // combine K-halves + bias + relu -> g_h3 in NCHW order
    for (int idx = tid; idx < 512; idx += 256) {
        int p = idx >> 5, oc = idx & 31;
        float v = s_c3[p*33 + oc] + s_c3[(16+p)*33 + oc] + __ldg(b3 + oc);
        g_h3[f*512 + oc*16 + p] = fmaxf(v, 0.f);
    }
}

// ---------------- 3xTF32 tensor-core GEMM: C = ep(A @ W^T [+ bias]) ----------------
// Block tile 64(M) x 128(N), BK=32, 256 threads = 8 warps (2x4 of 32x32).
// mode 0: A plain [*,lda]. mode 1: A row b = [r(b,:) | h(b,:)] (512 cols).
// ep 0: partial (C + z*partStride, no bias). ep 1: +bias. ep 2: +bias, relu.
__global__ void __launch_bounds__(256) k_tc(
    const float* __restrict__ A, int lda,
    const float* __restrict__ W, int ldw,
    const float* __restrict__ bias,
    float* __restrict__ C, int ldc,
    int Ksplit, int partStride, int mode, int ep)
{
    __shared__ float sA[32][72];
    __shared__ float sW[32][136];

    const int tid = threadIdx.x;
    const int warpid = tid >> 5, lane = tid & 31;
    const int g = lane >> 2, tig = lane & 3;
    const int wm = warpid >> 2, wn = warpid & 3;
    const int mtile = blockIdx.y, ntile = blockIdx.x, z = blockIdx.z;
    const int kStart = z * Ksplit;

    const float* Ab; int abase;
    int ldae;
    if (mode == 1) {
        if (kStart < KSZ) { Ab = g_r;  abase = kStart; }
        else              { Ab = g_hst; abase = kStart - KSZ; }
        ldae = 256;
    } else { Ab = A; abase = kStart; ldae = lda; }
    float* Cp = C + z * partStride;

    const int aidx0 = tid,        aidx1 = tid + 256;
    const int arow0 = aidx0 & 63, akq0 = aidx0 >> 6;
    const int arow1 = aidx1 & 63, akq1 = aidx1 >> 6;
    const float* Abase0 = Ab + (mtile*64 + arow0)*ldae + abase + akq0*4;
    const float* Abase1 = Ab + (mtile*64 + arow1)*ldae + abase + akq1*4;

    float acc[2][4][4];
    #pragma unroll
    for (int mi = 0; mi < 2; mi++)
        #pragma unroll
        for (int ni = 0; ni < 4; ni++)
            #pragma unroll
            for (int q = 0; q < 4; q++) acc[mi][ni][q] = 0.f;

    const int nkc = Ksplit >> 5;
    float4 pa0 = *(const float4*)(Abase0);
    float4 pa1 = *(const float4*)(Abase1);
    float4 pw[4];
    #pragma unroll
    for (int q = 0; q < 4; q++) {
        int idx = tid + q*256;
        int n = idx & 127, kq = idx >> 7;
        pw[q] = *(const float4*)(W + (ntile*128 + n)*ldw + kStart + kq*4);
    }

    for (int kt = 0; kt < nkc; kt++) {
        sA[akq0*4+0][arow0] = pa0.x; sA[akq0*4+1][arow0] = pa0.y;
        sA[akq0*4+2][arow0] = pa0.z; sA[akq0*4+3][arow0] = pa0.w;
        sA[akq1*4+0][arow1] = pa1.x; sA[akq1*4+1][arow1] = pa1.y;
        sA[akq1*4+2][arow1] = pa1.z; sA[akq1*4+3][arow1] = pa1.w;
        #pragma unroll
        for (int q = 0; q < 4; q++) {
            int idx = tid + q*256;
            int n = idx & 127, kq = idx >> 7;
            sW[kq*4+0][n] = pw[q].x; sW[kq*4+1][n] = pw[q].y;
            sW[kq*4+2][n] = pw[q].z; sW[kq*4+3][n] = pw[q].w;
        }
        __syncthreads();

        if (kt + 1 < nkc) {
            int kb = (kt+1) << 5;
            pa0 = *(const float4*)(Abase0 + kb);
            pa1 = *(const float4*)(Abase1 + kb);
            #pragma unroll
            for (int q = 0; q < 4; q++) {
                int idx = tid + q*256;
                int n = idx & 127, kq = idx >> 7;
                pw[q] = *(const float4*)(W + (ntile*128 + n)*ldw + kStart + kb + kq*4);
            }
        }

        #pragma unroll
        for (int kk = 0; kk < 4; kk++) {
            const int k0 = kk*8 + tig, k1 = k0 + 4;
            unsigned ahi[2][4], alo[2][4], bhi[4][2], blo[4][2];
            #pragma unroll
            for (int mi = 0; mi < 2; mi++) {
                int r0 = wm*32 + mi*16 + g;
                split2(sA[k0][r0],    ahi[mi][0], alo[mi][0]);
                split2(sA[k0][r0+8],  ahi[mi][1], alo[mi][1]);
                split2(sA[k1][r0],    ahi[mi][2], alo[mi][2]);
                split2(sA[k1][r0+8],  ahi[mi][3], alo[mi][3]);
            }
            #pragma unroll
            for (int ni = 0; ni < 4; ni++) {
                int c0 = wn*32 + ni*8 + g;
                split2(sW[k0][c0], bhi[ni][0], blo[ni][0]);
                split2(sW[k1][c0], bhi[ni][1], blo[ni][1]);
            }
            #pragma unroll
            for (int mi = 0; mi < 2; mi++)
                #pragma unroll
                for (int ni = 0; ni < 4; ni++) {
                    mma8(acc[mi][ni], ahi[mi], bhi[ni]);
                    mma8(acc[mi][ni], alo[mi], bhi[ni]);
                    mma8(acc[mi][ni], ahi[mi], blo[ni]);
                }
        }
        __syncthreads();
    }

    #pragma unroll
    for (int mi = 0; mi < 2; mi++) {
        #pragma unroll
        for (int ni = 0; ni < 4; ni++) {
            int row0 = mtile*64 + wm*32 + mi*16 + g;
            int col0 = ntile*128 + wn*32 + ni*8 + 2*tig;
            float v0 = acc[mi][ni][0], v1 = acc[mi][ni][1];
            float v2 = acc[mi][ni][2], v3 = acc[mi][ni][3];
            if (ep >= 1) {
                float b0 = bias[col0], b1 = bias[col0+1];
                v0 += b0; v1 += b1; v2 += b0; v3 += b1;
            }
            if (ep == 2) {
                v0 = fmaxf(v0, 0.f); v1 = fmaxf(v1, 0.f);
                v2 = fmaxf(v2, 0.f); v3 = fmaxf(v3, 0.f);
            }
            float* p = Cp + row0*ldc + col0;
            p[0] = v0; p[1] = v1;
            p[8*ldc] = v2; p[8*ldc + 1] = v3;
        }
    }
}

// ---------------- context norm over time, fused fc2 combine + bias + relu ------------
__global__ void k_ctxnorm(const float* __restrict__ fc2b,
                          const float* __restrict__ gamma, const float* __restrict__ beta)
{
    int b = blockIdx.x, d = threadIdx.x;
    float bias = fc2b[d];
    float v[TT];
    float s = 0.f, s2 = 0.f;
    #pragma unroll
    for (int t = 0; t < TT; t++) {
        int idx = (b*TT+t)*DD + d;
        v[t] = fmaxf(g_fc2p[idx] + g_fc2p[NFRM*DD + idx] + bias, 0.f);
        s += v[t]; s2 += v[t]*v[t];
    }
    float mu  = s / TT;
    float var = (s2 - TT*mu*mu) / (TT - 1);
    float inv = 1.f / sqrtf(var + EPSF);
    float ga = gamma[d], be = beta[d];
    #pragma unroll
    for (int t = 0; t < TT; t++)
        g_z[(b*TT+t)*DD + d] = (v[t] - mu)*inv*ga + be;
}

// ---------------- setup (incl. conv weight restaging to fragment order) -------------
__global__ void k_setup(const float* __restrict__ mem0,
                        const float* __restrict__ wi, const float* __restrict__ wh,
                        const float* __restrict__ wk, const float* __restrict__ wwk,
                        const float* __restrict__ wv,
                        const float* __restrict__ w2, const float* __restrict__ w3,
                        float* __restrict__ out, int out_size)
{
    int i = blockIdx.x*256 + threadIdx.x;
    if (i < BB*MEMN*KSZ) g_M[i] = mem0[i % (MEMN*KSZ)];
    if (i < 1024*512) {
        int j = i >> 9, c = i & 511;
        g_Wcat[i] = (c < 256) ? wi[j*384 + 128 + c] : wh[j*256 + (c-256)];
    }
    if (i < 1024*128) {
        int j = i >> 7, c = i & 127;
        g_Wz[i] = wi[j*384 + c];
    }
    if (i < 768*256) {
        int n = i >> 8;
        g_Whead[i] = (n < 256) ? wk[i] : ((n < 512) ? wwk[i - 256*256] : wv[i - 512*256]);
    }
    if (i < 16384) {
        int lane = i & 31;
        int j = i >> 5;
        int n8i = j & 3; j >>= 2;
        int half = j & 1; j >>= 1;
        int ick = j & 3;
        int khw = j >> 2;
        int n = n8i*8 + (lane >> 2);
        int kic = ick*8 + (lane & 3) + half*4;
        g_w2r[i] = w2[n*512 + kic*16 + khw];
        g_w3r[i] = w3[n*512 + kic*16 + khw];
    }
    if (i < BB*HH) { g_hst[i] = 0.f; g_cst[i] = 0.f; }
    if (i < BB*KSZ) g_r[i] = 0.f;
    if (i < out_size) out[i] = 0.f;
}

// ---------------- per-step: LSTM update (sums gz + 4 gate partials, float4) ----------
__global__ void k_lstm(int t)
{
    int idx = blockIdx.x*256 + threadIdx.x;
    int b = idx >> 6, j = (idx & 63) << 2;
    const float* gz = g_gz + (b*TT + t)*1024;
    float4 g[4];
    #pragma unroll
    for (int gt = 0; gt < 4; gt++) g[gt] = *(const float4*)(gz + gt*256 + j);
    #pragma unroll
    for (int z = 0; z < 4; z++) {
        const float* gp = g_gates4 + z*(BB*1024) + b*1024;
        #pragma unroll
        for (int gt = 0; gt < 4; gt++) {
            float4 p = *(const float4*)(gp + gt*256 + j);
            g[gt].x += p.x; g[gt].y += p.y; g[gt].z += p.z; g[gt].w += p.w;
        }
    }
    float4 c = *(const float4*)(g_cst + b*HH + j);
    float4 cn, hn;
    cn.x = sigmf(g[1].x)*c.x + sigmf(g[0].x)*tanhf(g[2].x);
    cn.y = sigmf(g[1].y)*c.y + sigmf(g[0].y)*tanhf(g[2].y);
    cn.z = sigmf(g[1].z)*c.z + sigmf(g[0].z)*tanhf(g[2].z);
    cn.w = sigmf(g[1].w)*c.w + sigmf(g[0].w)*tanhf(g[2].w);
    hn.x = sigmf(g[3].x)*tanhf(cn.x);
    hn.y = sigmf(g[3].y)*tanhf(cn.y);
    hn.z = sigmf(g[3].z)*tanhf(cn.z);
    hn.w = sigmf(g[3].w)*tanhf(cn.w);
    *(float4*)(g_cst + b*HH + j) = cn;
    *(float4*)(g_hst + b*HH + j) = hn;
}

// ---------------- per-step: memory read/write + (last step) output ----------------
__global__ void __launch_bounds__(256) k_mem(int t, const float* __restrict__ wo,
                                             const float* __restrict__ wob,
                                             float* __restrict__ out, int out_size)
{
    __shared__ float s_kr[256], s_kw[256], s_rnew[256];
    __shared__ float s_simr[MEMN], s_simw[MEMN];
    __shared__ float s_wr[4], s_ws[4];
    __shared__ int   s_ir[4], s_iw[4];
    __shared__ float s_red[16];
    __shared__ float s_nrm[2];
    __shared__ float s_y[4];

    int b = blockIdx.x, tid = threadIdx.x;
    int lane = tid & 31, wid = tid >> 5;

    float kr = 0.f, kw = 0.f, vvs = 0.f;
    #pragma unroll
    for (int z = 0; z < 4; z++) {
        const float* hp = g_hpart + z*(BB*768) + b*768;
        kr  += hp[tid];
        kw  += hp[256 + tid];
        vvs += hp[512 + tid];
    }
    float vv = tanhf(vvs);
    s_kr[tid] = kr;
    s_kw[tid] = kw;

    float pr = kr*kr, pw = kw*kw;
    #pragma unroll
    for (int o = 16; o > 0; o >>= 1) {
        pr += __shfl_xor_sync(0xffffffffu, pr, o);
        pw += __shfl_xor_sync(0xffffffffu, pw, o);
    }
    if (lane == 0) { s_red[wid] = pr; s_red[8 + wid] = pw; }
    __syncthreads();
    if (tid == 0) {
        float sr = 0.f, sw = 0.f;
        #pragma unroll
        for (int w = 0; w < 8; w++) { sr += s_red[w]; sw += s_red[8 + w]; }
        s_nrm[0] = 1.f / (sqrtf(sr) + EPSF);
        s_nrm[1] = 1.f / (sqrtf(sw) + EPSF);
    }
    __syncthreads();

    for (int n = wid; n < MEMN; n += 8) {
        const float* Mr = g_M + (b*MEMN + n)*KSZ;
        float dr = 0.f, dw = 0.f, nn = 0.f;
        #pragma unroll
        for (int d0 = 0; d0 < KSZ; d0 += 32) {
            float m = Mr[d0 + lane];
            dr += s_kr[d0 + lane]*m;
            dw += s_kw[d0 + lane]*m;
            nn += m*m;
        }
        #pragma unroll
        for (int o = 16; o > 0; o >>= 1) {
            dr += __shfl_xor_sync(0xffffffffu, dr, o);
            dw += __shfl_xor_sync(0xffffffffu, dw, o);
            nn += __shfl_xor_sync(0xffffffffu, nn, o);
        }
        if (lane == 0) {
            float mi = 1.f / (sqrtf(nn) + EPSF);
            s_simr[n] = dr * s_nrm[0] * mi;
            s_simw[n] = dw * s_nrm[1] * mi;
        }
    }
    __syncthreads();

    if (tid < 2) {
        const float* sims = tid ? s_simw : s_simr;
        float* wout = tid ? s_ws : s_wr;
        int*   iout = tid ? s_iw : s_ir;
        unsigned used = 0;
        float vals[4];
        #pragma unroll
        for (int k = 0; k < 4; k++) {
            float best = -1e30f; int bi = 0;
            for (int n = 0; n < MEMN; n++) {
                if (!((used >> n) & 1u) && sims[n] > best) { best = sims[n]; bi = n; }
            }
            used |= 1u << bi;
            iout[k] = bi; vals[k] = best;
        }
        float mx = vals[0], ssum = 0.f, e[4];
        #pragma unroll
        for (int k = 0; k < 4; k++) { e[k] = expf(vals[k] - mx); ssum += e[k]; }
        #pragma unroll
        for (int k = 0; k < 4; k++) wout[k] = e[k] / ssum;
    }
    __syncthreads();

    float r = 0.f;
    #pragma unroll
    for (int k = 0; k < 4; k++)
        r += s_wr[k] * g_M[(b*MEMN + s_ir[k])*KSZ + tid];
    g_r[b*KSZ + tid] = r;
    s_rnew[tid] = r;

    #pragma unroll
    for (int k = 0; k < 4; k++)
        g_M[(b*MEMN + s_iw[k])*KSZ + tid] += s_ws[k] * vv;

    if (t == TT - 1) {
        __syncthreads();
        if (wid < 4) {
            const float* wrow = wo + wid*512;
            float p = 0.f;
            for (int j = lane; j < 256; j += 32) p += wrow[j]       * g_hst[b*HH + j];
            for (int j = lane; j < 256; j += 32) p += wrow[256 + j] * s_rnew[j];
            #pragma unroll
            for (int o = 16; o > 0; o >>= 1) p += __shfl_xor_sync(0xffffffffu, p, o);
            if (lane == 0) s_y[wid] = p + wob[wid];
        }
        __syncthreads();
        if (tid < 4 && (b*4 + tid) < out_size) out[b*4 + tid] = s_y[tid];
        if (tid == 0 && out_size >= BB*YY + BB) {
            int am = 0; float bv = s_y[0];
            #pragma unroll
            for (int o = 1; o < 4; o++) if (s_y[o] > bv) { bv = s_y[o]; am = o; }
            out[BB*YY + b] = (float)am;
        }
    }
}

// ---------------- launch ----------------
extern "C" void kernel_launch(void* const* d_in, const int* in_sizes, int n_in,
                              void* d_out, int out_size)
{
    const float* x    = (const float*)d_in[0];
    const float* c1w  = (const float*)d_in[1];
    const float* c1b  = (const float*)d_in[2];
    const float* c2w  = (const float*)d_in[3];
    const float* c2b  = (const float*)d_in[4];
    const float* c3w  = (const float*)d_in[5];
    const float* c3b  = (const float*)d_in[6];
    const float* fc1w = (const float*)d_in[7];
    const float* fc1b = (const float*)d_in[8];
    const float* fc2w = (const float*)d_in[9];
    const float* fc2b = (const float*)d_in[10];
    const float* gamma= (const float*)d_in[11];
    const float* beta = (const float*)d_in[12];
    const float* lwi  = (const float*)d_in[13];
    const float* lwh  = (const float*)d_in[14];
    const float* lb   = (const float*)d_in[15];
    const float* wk   = (const float*)d_in[16];
    const float* wwk  = (const float*)d_in[17];
    const float* wv   = (const float*)d_in[18];
    const float* wo   = (const float*)d_in[19];
    const float* wob  = (const float*)d_in[20];
    const float* mem0 = (const float*)d_in[21];
    float* out = (float*)d_out;

    cudaFuncSetAttribute(k_convf, cudaFuncAttributeMaxDynamicSharedMemorySize,
                         CONVF_SMEM_FLOATS * 4);

    float *p_h3, *p_fc1, *p_fc2p, *p_z, *p_gz, *p_g4, *p_hp, *p_h;
    float *p_wcat, *p_wz, *p_whead, *p_w2r, *p_w3r;
    cudaGetSymbolAddress((void**)&p_h3,    g_h3);
    cudaGetSymbolAddress((void**)&p_fc1,   g_fc1);
    cudaGetSymbolAddress((void**)&p_fc2p,  g_fc2p);
    cudaGetSymbolAddress((void**)&p_z,     g_z);
    cudaGetSymbolAddress((void**)&p_gz,    g_gz);
    cudaGetSymbolAddress((void**)&p_g4,    g_gates4);
    cudaGetSymbolAddress((void**)&p_hp,    g_hpart);
    cudaGetSymbolAddress((void**)&p_h,     g_hst);
    cudaGetSymbolAddress((void**)&p_wcat,  g_Wcat);
    cudaGetSymbolAddress((void**)&p_wz,    g_Wz);
    cudaGetSymbolAddress((void**)&p_whead, g_Whead);
    cudaGetSymbolAddress((void**)&p_w2r,   g_w2r);
    cudaGetSymbolAddress((void**)&p_w3r,   g_w3r);

    k_setup<<<(BB*MEMN*KSZ + 255)/256, 256>>>(mem0, lwi, lwh, wk, wwk, wv,
                                              c2w, c3w, out, out_size);

    // encoder (tensor-core conv)
    k_convf<<<NFRM, 256, CONVF_SMEM_FLOATS * 4>>>(x, c1w, c1b, p_w2r, c2b, p_w3r, c3b);
    // fc1: [5120,512]@[256,512]^T + b -> relu (tensor cores)
    k_tc<<<dim3(2, 80, 1), 256>>>(p_h3, 512, fc1w, 512, fc1b, p_fc1, 256, 512, 0, 0, 2);
    // fc2: split-K x2 partials; combine in ctxnorm
    k_tc<<<dim3(1, 80, 2), 256>>>(p_fc1, 256, fc2w, 256, nullptr, p_fc2p, 128,
                                  128, NFRM*DD, 0, 0);
    k_ctxnorm<<<BB, 128>>>(fc2b, gamma, beta);
    // Gz = z @ Wz^T + lstm_b for all (b,t)
    k_tc<<<dim3(8, 80, 1), 256>>>(p_z, 128, p_wz, 128, lb, p_gz, 1024, 128, 0, 0, 1);

    for (int t = 0; t < TT; t++) {
        // gates: [r|h] @ Wcat^T, split-K x4
        k_tc<<<dim3(8, 4, 4), 256>>>(nullptr, 0, p_wcat, 512, nullptr, p_g4, 1024,
                                     128, BB*1024, 1, 0);
        k_lstm<<<64, 256>>>(t);
        // heads: h @ Whead^T, split-K x4
        k_tc<<<dim3(6, 4, 4), 256>>>(p_h, 256, p_whead, 256, nullptr, p_hp, 768,
                                     64, BB*768, 0, 0);
        k_mem<<<BB, 256>>>(t, wo, wob, out, out_size);
    }
}

// round 8
// speedup vs baseline: 1.4963x; 1.0250x over previous
#include <cuda_runtime.h>
#include <math.h>

#define BB 256
#define TT 20
#define DD 128
#define HH 256
#define KSZ 256
#define MEMN 20
#define YY 4
#define EPSF 1e-8f
#define NFRM (BB*TT)

// ---------------- device scratch ----------------
__device__ float g_h3[NFRM*512];
__device__ float g_fc1[NFRM*256];
__device__ float g_fc2p[2*NFRM*DD];     // fc2 split-K partials
__device__ float g_z[NFRM*DD];
__device__ float g_gz[NFRM*1024];       // precomputed z@Wz^T + lstm_b
__device__ float g_gates4[4*BB*1024];   // gates split-K partials
__device__ float g_hpart[2*BB*768];     // heads split-K partials
__device__ float g_hst[BB*HH];
__device__ float g_cst[BB*HH];
__device__ float g_r[BB*KSZ];
__device__ float g_M[BB*MEMN*KSZ];
__device__ float g_Wcat[1024*512];      // [Wr | Wh]
__device__ float g_Wz[1024*128];
__device__ float g_Whead[768*256];
__device__ float g_w2r[16384];          // conv2 weights, mma-fragment order
__device__ float g_w3r[16384];          // conv3 weights, mma-fragment order

__device__ __forceinline__ float sigmf(float x){ return 1.f/(1.f+expf(-x)); }

// ---------------- tf32 mma helpers ----------------
__device__ __forceinline__ void mma8(float* c, const unsigned* a, const unsigned* b)
{
    asm volatile(
        "mma.sync.aligned.m16n8k8.row.col.f32.tf32.tf32.f32 "
        "{%0,%1,%2,%3},{%4,%5,%6,%7},{%8,%9},{%0,%1,%2,%3};"
        : "+f"(c[0]), "+f"(c[1]), "+f"(c[2]), "+f"(c[3])
        : "r"(a[0]), "r"(a[1]), "r"(a[2]), "r"(a[3]), "r"(b[0]), "r"(b[1]));
}
__device__ __forceinline__ void split2(float x, unsigned& hi, unsigned& lo)
{
    unsigned h = __float_as_uint(x) & 0xffffe000u;   // exact tf32 (truncated)
    hi = h;
    lo = __float_as_uint(x - __uint_as_float(h));
}
__device__ __forceinline__ void cpasync16(unsigned dst, const void* src)
{
    asm volatile("cp.async.cg.shared.global [%0], [%1], 16;\n" :: "r"(dst), "l"(src));
}

// ---------------- fused conv encoder (tensor-core conv2/conv3) ----------------
#define S_H1 1156
#define S_H2 13144
#define S_C3 16844
#define CONVF_SMEM_FLOATS 17900

__global__ void __launch_bounds__(256, 2) k_convf(
    const float* __restrict__ x,
    const float* __restrict__ w1, const float* __restrict__ b1,
    const float* __restrict__ w2r, const float* __restrict__ b2,
    const float* __restrict__ w3r, const float* __restrict__ b3)
{
    extern __shared__ float sm[];
    float* s_in = sm;
    float* s_h1 = sm + S_H1;
    float* s_h2 = sm + S_H2;
    float* s_c3 = sm + S_C3;
    const int f = blockIdx.x, tid = threadIdx.x;
    const int lane = tid & 31, warpid = tid >> 5;
    const int g = lane >> 2, tig = lane & 3;

    for (int i = tid; i < S_C3; i += 256) sm[i] = 0.f;
    __syncthreads();
    for (int i = tid; i < 1024; i += 256) {
        int iy = i >> 5, ix = i & 31;
        s_in[(iy+1)*34 + ix + 1] = x[f*1024 + i];
    }
    __syncthreads();

    // ---- conv1 (FFMA): 1->32ch, 32x32 -> 16x16, write channel-last ----
    for (int p = tid; p < 512; p += 256) {
        int oc = p >> 4, oy = p & 15;
        float bias = __ldg(b1 + oc);
        float acc[16];
        #pragma unroll
        for (int ox = 0; ox < 16; ox++) acc[ox] = bias;
        #pragma unroll
        for (int kh = 0; kh < 4; kh++) {
            const float* row = s_in + (2*oy+kh)*34;
            const float4 w = __ldg((const float4*)(w1 + oc*16 + kh*4));
            #pragma unroll
            for (int ox = 0; ox < 16; ox++) {
                acc[ox] += row[2*ox]*w.x + row[2*ox+1]*w.y
                         + row[2*ox+2]*w.z + row[2*ox+3]*w.w;
            }
        }
        int cellbase = (oy+1)*18 + 1;
        #pragma unroll
        for (int ox = 0; ox < 16; ox++)
            s_h1[(cellbase + ox)*37 + oc] = fmaxf(acc[ox], 0.f);
    }
    __syncthreads();

    // ---- conv2 (tf32 mma) ----
    {
        const int wm = warpid & 3, wn = warpid >> 2;
        float acc[2][4] = {{0.f,0.f,0.f,0.f},{0.f,0.f,0.f,0.f}};
        int pA = wm*16 + g, pB = pA + 8;
        int oyA = pA >> 3, oxA = pA & 7;
        int oyB = pB >> 3, oxB = pB & 7;
        #pragma unroll 1
        for (int khw = 0; khw < 16; khw++) {
            int kh = khw >> 2, kw = khw & 3;
            const float* hA = s_h1 + ((2*oyA + kh)*18 + 2*oxA + kw)*37;
            const float* hB = s_h1 + ((2*oyB + kh)*18 + 2*oxB + kw)*37;
            #pragma unroll
            for (int ick = 0; ick < 4; ick++) {
                int ic0 = ick*8;
                unsigned ahi[4], alo[4];
                split2(hA[ic0+tig],   ahi[0], alo[0]);
                split2(hB[ic0+tig],   ahi[1], alo[1]);
                split2(hA[ic0+tig+4], ahi[2], alo[2]);
                split2(hB[ic0+tig+4], ahi[3], alo[3]);
                int idx128 = (khw*4 + ick)*2;
                #pragma unroll
                for (int ni = 0; ni < 2; ni++) {
                    int n8i = wn*2 + ni;
                    unsigned bhi[2], blo[2];
                    float b0 = __ldg(w2r + ((idx128+0)*4 + n8i)*32 + lane);
                    float b1v= __ldg(w2r + ((idx128+1)*4 + n8i)*32 + lane);
                    split2(b0,  bhi[0], blo[0]);
                    split2(b1v, bhi[1], blo[1]);
                    mma8(acc[ni], ahi, bhi);
                    mma8(acc[ni], alo, bhi);
                    mma8(acc[ni], ahi, blo);
                }
            }
        }
        int cellA = (oyA+1)*10 + oxA + 1;
        int cellB = (oyB+1)*10 + oxB + 1;
        #pragma unroll
        for (int ni = 0; ni < 2; ni++) {
            int col0 = wn*16 + ni*8 + 2*tig;
            float bb0 = __ldg(b2 + col0), bb1 = __ldg(b2 + col0 + 1);
            s_h2[cellA*37 + col0]     = fmaxf(acc[ni][0] + bb0, 0.f);
            s_h2[cellA*37 + col0 + 1] = fmaxf(acc[ni][1] + bb1, 0.f);
            s_h2[cellB*37 + col0]     = fmaxf(acc[ni][2] + bb0, 0.f);
            s_h2[cellB*37 + col0 + 1] = fmaxf(acc[ni][3] + bb1, 0.f);
        }
    }
    __syncthreads();

    // ---- conv3 (tf32 mma, 2-way K-split across warps) ----
    {
        const int n8i = warpid & 3, khalf = warpid >> 2;
        float acc[4] = {0.f, 0.f, 0.f, 0.f};
        int pA = g, pB = g + 8;
        int oyA = pA >> 2, oxA = pA & 3;
        int oyB = pB >> 2, oxB = pB & 3;
        #pragma unroll 1
        for (int kk = 0; kk < 8; kk++) {
            int khw = khalf*8 + kk;
            int kh = khw >> 2, kw = khw & 3;
            const float* hA = s_h2 + ((2*oyA + kh)*10 + 2*oxA + kw)*37;
            const float* hB = s_h2 + ((2*oyB + kh)*10 + 2*oxB + kw)*37;
            #pragma unroll
            for (int ick = 0; ick < 4; ick++) {
                int ic0 = ick*8;
                unsigned ahi[4], alo[4];
                split2(hA[ic0+tig],   ahi[0], alo[0]);
                split2(hB[ic0+tig],   ahi[1], alo[1]);
                split2(hA[ic0+tig+4], ahi[2], alo[2]);
                split2(hB[ic0+tig+4], ahi[3], alo[3]);
                int idx128 = (khw*4 + ick)*2;
                unsigned bhi[2], blo[2];
                float b0 = __ldg(w3r + ((idx128+0)*4 + n8i)*32 + lane);
                float b1v= __ldg(w3r + ((idx128+1)*4 + n8i)*32 + lane);
                split2(b0,  bhi[0], blo[0]);
                split2(b1v, bhi[1], blo[1]);
                mma8(acc, ahi, bhi);
                mma8(acc, alo, bhi);
                mma8(acc, ahi, blo);
            }
        }
        int col0 = n8i*8 + 2*tig;
        s_c3[(khalf*16 + g)*33 + col0]       = acc[0];
        s_c3[(khalf*16 + g)*33 + col0 + 1]   = acc[1];
        s_c3[(khalf*16 + g+8)*33 + col0]     = acc[2];
        s_c3[(khalf*16 + g+8)*33 + col0 + 1] = acc[3];
    }
    __syncthreads();
    for (int idx = tid; idx < 512; idx += 256) {
        int p = idx >> 5, oc = idx & 31;
        float v = s_c3[p*33 + oc] + s_c3[(16+p)*33 + oc] + __ldg(b3 + oc);
        g_h3[f*512 + oc*16 + p] = fmaxf(v, 0.f);
    }
}

// ---------------- chunked 3xTF32 GEMM (used for fc1, K=512) ----------------
__global__ void __launch_bounds__(256) k_tc(
    const float* __restrict__ A, int lda,
    const float* __restrict__ W, int ldw,
    const float* __restrict__ bias,
    float* __restrict__ C, int ldc, int K, int ep)
{
    __shared__ float sA[32][72];
    __shared__ float sW[32][136];

    const int tid = threadIdx.x;
    const int warpid = tid >> 5, lane = tid & 31;
    const int g = lane >> 2, tig = lane & 3;
    const int wm = warpid >> 2, wn = warpid & 3;
    const int mtile = blockIdx.y, ntile = blockIdx.x;

    const int arow0 = tid & 63, akq0 = tid >> 6;
    const int arow1 = arow0, akq1 = akq0 + 4;
    const float* Abase0 = A + (mtile*64 + arow0)*lda + akq0*4;
    const float* Abase1 = A + (mtile*64 + arow1)*lda + akq1*4;

    float acc[2][4][4];
    #pragma unroll
    for (int mi = 0; mi < 2; mi++)
        #pragma unroll
        for (int ni = 0; ni < 4; ni++)
            #pragma unroll
            for (int q = 0; q < 4; q++) acc[mi][ni][q] = 0.f;

    const int nkc = K >> 5;
    float4 pa0 = *(const float4*)(Abase0);
    float4 pa1 = *(const float4*)(Abase1);
    float4 pw[4];
    #pragma unroll
    for (int q = 0; q < 4; q++) {
        int idx = tid + q*256;
        int n = idx & 127, kq = idx >> 7;
        pw[q] = *(const float4*)(W + (ntile*128 + n)*ldw + kq*4);
    }

    for (int kt = 0; kt < nkc; kt++) {
        sA[akq0*4+0][arow0] = pa0.x; sA[akq0*4+1][arow0] = pa0.y;
        sA[akq0*4+2][arow0] = pa0.z; sA[akq0*4+3][arow0] = pa0.w;
        sA[akq1*4+0][arow1] = pa1.x; sA[akq1*4+1][arow1] = pa1.y;
        sA[akq1*4+2][arow1] = pa1.z; sA[akq1*4+3][arow1] = pa1.w;
        #pragma unroll
        for (int q = 0; q < 4; q++) {
            int idx = tid + q*256;
            int n = idx & 127, kq = idx >> 7;
            sW[kq*4+0][n] = pw[q].x; sW[kq*4+1][n] = pw[q].y;
            sW[kq*4+2][n] = pw[q].z; sW[kq*4+3][n] = pw[q].w;
        }
        __syncthreads();

        if (kt + 1 < nkc) {
            int kb = (kt+1) << 5;
            pa0 = *(const float4*)(Abase0 + kb);
            pa1 = *(const float4*)(Abase1 + kb);
            #pragma unroll
            for (int q = 0; q < 4; q++) {
                int idx = tid + q*256;
                int n = idx & 127, kq = idx >> 7;
                pw[q] = *(const float4*)(W + (ntile*128 + n)*ldw + kb + kq*4);
            }
        }

        #pragma unroll
        for (int kk = 0; kk < 4; kk++) {
            const int k0 = kk*8 + tig, k1 = k0 + 4;
            unsigned ahi[2][4], alo[2][4], bhi[4][2], blo[4][2];
            #pragma unroll
            for (int mi = 0; mi < 2; mi++) {
                int r0 = wm*32 + mi*16 + g;
                split2(sA[k0][r0],    ahi[mi][0], alo[mi][0]);
                split2(sA[k0][r0+8],  ahi[mi][1], alo[mi][1]);
                split2(sA[k1][r0],    ahi[mi][2], alo[mi][2]);
                split2(sA[k1][r0+8],  ahi[mi][3], alo[mi][3]);
            }
            #pragma unroll
            for (int ni = 0; ni < 4; ni++) {
                int c0 = wn*32 + ni*8 + g;
                split2(sW[k0][c0], bhi[ni][0], blo[ni][0]);
                split2(sW[k1][c0], bhi[ni][1], blo[ni][1]);
            }
            #pragma unroll
            for (int mi = 0; mi < 2; mi++)
                #pragma unroll
                for (int ni = 0; ni < 4; ni++) {
                    mma8(acc[mi][ni], ahi[mi], bhi[ni]);
                    mma8(acc[mi][ni], alo[mi], bhi[ni]);
                    mma8(acc[mi][ni], ahi[mi], blo[ni]);
                }
        }
        __syncthreads();
    }

    #pragma unroll
    for (int mi = 0; mi < 2; mi++) {
        #pragma unroll
        for (int ni = 0; ni < 4; ni++) {
            int row0 = mtile*64 + wm*32 + mi*16 + g;
            int col0 = ntile*128 + wn*32 + ni*8 + 2*tig;
            float v0 = acc[mi][ni][0], v1 = acc[mi][ni][1];
            float v2 = acc[mi][ni][2], v3 = acc[mi][ni][3];
            if (ep >= 1) {
                float b0 = bias[col0], b1 = bias[col0+1];
                v0 += b0; v1 += b1; v2 += b0; v3 += b1;
            }
            if (ep == 2) {
                v0 = fmaxf(v0, 0.f); v1 = fmaxf(v1, 0.f);
                v2 = fmaxf(v2, 0.f); v3 = fmaxf(v3, 0.f);
            }
            float* p = C + row0*ldc + col0;
            p[0] = v0; p[1] = v1;
            p[8*ldc] = v2; p[8*ldc + 1] = v3;
        }
    }
}

// ---------------- single-stage 3xTF32 GEMM (K=128 per block, cp.async) -------------
// 64(M) x 128(N) tile, full 128-K slab staged once, one sync, straight-line mma.
// mode 0: A plain. mode 1: A row b = [r | h] selected by kStart.
// ep 0: partial to C + z*partStride (no bias). ep 1: +bias.
#define TCS_SMEM_BYTES ((64*132 + 128*132)*4)

__global__ void __launch_bounds__(256) k_tcs(
    const float* __restrict__ A, int lda,
    const float* __restrict__ W, int ldw,
    const float* __restrict__ bias,
    float* __restrict__ C, int ldc,
    int partStride, int mode, int ep)
{
    extern __shared__ float smem[];
    float* sA = smem;            // [64][132] row-major
    float* sW = smem + 64*132;   // [128][132] row-major
    const int tid = threadIdx.x;
    const int warpid = tid >> 5, lane = tid & 31;
    const int g = lane >> 2, tig = lane & 3;
    const int wm = warpid >> 2, wn = warpid & 3;
    const int mtile = blockIdx.y, ntile = blockIdx.x, z = blockIdx.z;
    const int kStart = z*128;

    const float* Ab; int abase, ldae;
    if (mode == 1) {
        if (kStart < KSZ) { Ab = g_r;   abase = kStart; }
        else              { Ab = g_hst; abase = kStart - KSZ; }
        ldae = 256;
    } else { Ab = A; abase = kStart; ldae = lda; }
    float* Cp = C + z*partStride;

    #pragma unroll
    for (int q = 0; q < 8; q++) {
        int c = tid + q*256;
        int row = c >> 5, kc = c & 31;
        const float* src = Ab + (mtile*64 + row)*ldae + abase + kc*4;
        cpasync16((unsigned)__cvta_generic_to_shared(sA + row*132 + kc*4), src);
    }
    #pragma unroll
    for (int q = 0; q < 16; q++) {
        int c = tid + q*256;
        int col = c >> 5, kc = c & 31;
        const float* src = W + (ntile*128 + col)*ldw + kStart + kc*4;
        cpasync16((unsigned)__cvta_generic_to_shared(sW + col*132 + kc*4), src);
    }
    asm volatile("cp.async.commit_group;\n");
    asm volatile("cp.async.wait_group 0;\n");
    __syncthreads();

    float acc[2][4][4];
    #pragma unroll
    for (int mi = 0; mi < 2; mi++)
        #pragma unroll
        for (int ni = 0; ni < 4; ni++)
            #pragma unroll
            for (int q = 0; q < 4; q++) acc[mi][ni][q] = 0.f;

    #pragma unroll 2
    for (int kk = 0; kk < 16; kk++) {
        const int k0 = kk*8 + tig, k1 = k0 + 4;
        unsigned ahi[2][4], alo[2][4], bhi[4][2], blo[4][2];
        #pragma unroll
        for (int mi = 0; mi < 2; mi++) {
            const float* r0 = sA + (wm*32 + mi*16 + g)*132;
            const float* r1 = r0 + 8*132;
            split2(r0[k0], ahi[mi][0], alo[mi][0]);
            split2(r1[k0], ahi[mi][1], alo[mi][1]);
            split2(r0[k1], ahi[mi][2], alo[mi][2]);
            split2(r1[k1], ahi[mi][3], alo[mi][3]);
        }
        #pragma unroll
        for (int ni = 0; ni < 4; ni++) {
            const float* c0 = sW + (wn*32 + ni*8 + g)*132;
            split2(c0[k0], bhi[ni][0], blo[ni][0]);
            split2(c0[k1], bhi[ni][1], blo[ni][1]);
        }
        #pragma unroll
        for (int mi = 0; mi < 2; mi++)
            #pragma unroll
            for (int ni = 0; ni < 4; ni++) {
                mma8(acc[mi][ni], ahi[mi], bhi[ni]);
                mma8(acc[mi][ni], alo[mi], bhi[ni]);
                mma8(acc[mi][ni], ahi[mi], blo[ni]);
            }
    }

    #pragma unroll
    for (int mi = 0; mi < 2; mi++) {
        #pragma unroll
        for (int ni = 0; ni < 4; ni++) {
            int row0 = mtile*64 + wm*32 + mi*16 + g;
            int col0 = ntile*128 + wn*32 + ni*8 + 2*tig;
            float v0 = acc[mi][ni][0], v1 = acc[mi][ni][1];
            float v2 = acc[mi][ni][2], v3 = acc[mi][ni][3];
            if (ep >= 1) {
                float b0 = bias[col0], b1 = bias[col0+1];
                v0 += b0; v1 += b1; v2 += b0; v3 += b1;
            }
            float* p = Cp + row0*ldc + col0;
            p[0] = v0; p[1] = v1;
            p[8*ldc] = v2; p[8*ldc + 1] = v3;
        }
    }
}

// ---------------- context norm over time, fused fc2 combine + bias + relu ------------
__global__ void k_ctxnorm(const float* __restrict__ fc2b,
                          const float* __restrict__ gamma, const float* __restrict__ beta)
{
    int b = blockIdx.x, d = threadIdx.x;
    float bias = fc2b[d];
    float v[TT];
    float s = 0.f, s2 = 0.f;
    #pragma unroll
    for (int t = 0; t < TT; t++) {
        int idx = (b*TT+t)*DD + d;
        v[t] = fmaxf(g_fc2p[idx] + g_fc2p[NFRM*DD + idx] + bias, 0.f);
        s += v[t]; s2 += v[t]*v[t];
    }
    float mu  = s / TT;
    float var = (s2 - TT*mu*mu) / (TT - 1);
    float inv = 1.f / sqrtf(var + EPSF);
    float ga = gamma[d], be = beta[d];
    #pragma unroll
    for (int t = 0; t < TT; t++)
        g_z[(b*TT+t)*DD + d] = (v[t] - mu)*inv*ga + be;
}

// ---------------- setup ----------------
__global__ void k_setup(const float* __restrict__ mem0,
                        const float* __restrict__ wi, const float* __restrict__ wh,
                        const float* __restrict__ wk, const float* __restrict__ wwk,
                        const float* __restrict__ wv,
                        const float* __restrict__ w2, const float* __restrict__ w3,
                        float* __restrict__ out, int out_size)
{
    int i = blockIdx.x*256 + threadIdx.x;
    if (i < BB*MEMN*KSZ) g_M[i] = mem0[i % (MEMN*KSZ)];
    if (i < 1024*512) {
        int j = i >> 9, c = i & 511;
        g_Wcat[i] = (c < 256) ? wi[j*384 + 128 + c] : wh[j*256 + (c-256)];
    }
    if (i < 1024*128) {
        int j = i >> 7, c = i & 127;
        g_Wz[i] = wi[j*384 + c];
    }
    if (i < 768*256) {
        int n = i >> 8;
        g_Whead[i] = (n < 256) ? wk[i] : ((n < 512) ? wwk[i - 256*256] : wv[i - 512*256]);
    }
    if (i < 16384) {
        int lane = i & 31;
        int j = i >> 5;
        int n8i = j & 3; j >>= 2;
        int half = j & 1; j >>= 1;
        int ick = j & 3;
        int khw = j >> 2;
        int n = n8i*8 + (lane >> 2);
        int kic = ick*8 + (lane & 3) + half*4;
        g_w2r[i] = w2[n*512 + kic*16 + khw];
        g_w3r[i] = w3[n*512 + kic*16 + khw];
    }
    if (i < BB*HH) { g_hst[i] = 0.f; g_cst[i] = 0.f; }
    if (i < BB*KSZ) g_r[i] = 0.f;
    if (i < out_size) out[i] = 0.f;
}

// ---------------- per-step: LSTM update (sums gz + 4 gate partials, float4) ----------
__global__ void k_lstm(int t)
{
    int idx = blockIdx.x*256 + threadIdx.x;
    int b = idx >> 6, j = (idx & 63) << 2;
    const float* gz = g_gz + (b*TT + t)*1024;
    float4 g[4];
    #pragma unroll
    for (int gt = 0; gt < 4; gt++) g[gt] = *(const float4*)(gz + gt*256 + j);
    #pragma unroll
    for (int z = 0; z < 4; z++) {
        const float* gp = g_gates4 + z*(BB*1024) + b*1024;
        #pragma unroll
        for (int gt = 0; gt < 4; gt++) {
            float4 p = *(const float4*)(gp + gt*256 + j);
            g[gt].x += p.x; g[gt].y += p.y; g[gt].z += p.z; g[gt].w += p.w;
        }
    }
    float4 c = *(const float4*)(g_cst + b*HH + j);
    float4 cn, hn;
    cn.x = sigmf(g[1].x)*c.x + sigmf(g[0].x)*tanhf(g[2].x);
    cn.y = sigmf(g[1].y)*c.y + sigmf(g[0].y)*tanhf(g[2].y);
    cn.z = sigmf(g[1].z)*c.z + sigmf(g[0].z)*tanhf(g[2].z);
    cn.w = sigmf(g[1].w)*c.w + sigmf(g[0].w)*tanhf(g[2].w);
    hn.x = sigmf(g[3].x)*tanhf(cn.x);
    hn.y = sigmf(g[3].y)*tanhf(cn.y);
    hn.z = sigmf(g[3].z)*tanhf(cn.z);
    hn.w = sigmf(g[3].w)*tanhf(cn.w);
    *(float4*)(g_cst + b*HH + j) = cn;
    *(float4*)(g_hst + b*HH + j) = hn;
}

// ---------------- per-step: memory read/write + (last step) output ----------------
__global__ void __launch_bounds__(256) k_mem(int t, const float* __restrict__ wo,
                                             const float* __restrict__ wob,
                                             float* __restrict__ out, int out_size)
{
    __shared__ float s_kr[256], s_kw[256], s_rnew[256];
    __shared__ float s_simr[MEMN], s_simw[MEMN];
    __shared__ float s_wr[4], s_ws[4];
    __shared__ int   s_ir[4], s_iw[4];
    __shared__ float s_red[16];
    __shared__ float s_nrm[2];
    __shared__ float s_y[4];

    int b = blockIdx.x, tid = threadIdx.x;
    int lane = tid & 31, wid = tid >> 5;

    float kr = 0.f, kw = 0.f, vvs = 0.f;
    #pragma unroll
    for (int z = 0; z < 2; z++) {
        const float* hp = g_hpart + z*(BB*768) + b*768;
        kr  += hp[tid];
        kw  += hp[256 + tid];
        vvs += hp[512 + tid];
    }
    float vv = tanhf(vvs);
    s_kr[tid] = kr;
    s_kw[tid] = kw;

    float pr = kr*kr, pw = kw*kw;
    #pragma unroll
    for (int o = 16; o > 0; o >>= 1) {
        pr += __shfl_xor_sync(0xffffffffu, pr, o);
        pw += __shfl_xor_sync(0xffffffffu, pw, o);
    }
    if (lane == 0) { s_red[wid] = pr; s_red[8 + wid] = pw; }
    __syncthreads();
    if (tid == 0) {
        float sr = 0.f, sw = 0.f;
        #pragma unroll
        for (int w = 0; w < 8; w++) { sr += s_red[w]; sw += s_red[8 + w]; }
        s_nrm[0] = 1.f / (sqrtf(sr) + EPSF);
        s_nrm[1] = 1.f / (sqrtf(sw) + EPSF);
    }
    __syncthreads();

    for (int n = wid; n < MEMN; n += 8) {
        const float* Mr = g_M + (b*MEMN + n)*KSZ;
        float dr = 0.f, dw = 0.f, nn = 0.f;
        #pragma unroll
        for (int d0 = 0; d0 < KSZ; d0 += 32) {
            float m = Mr[d0 + lane];
            dr += s_kr[d0 + lane]*m;
            dw += s_kw[d0 + lane]*m;
            nn += m*m;
        }
        #pragma unroll
        for (int o = 16; o > 0; o >>= 1) {
            dr += __shfl_xor_sync(0xffffffffu, dr, o);
            dw += __shfl_xor_sync(0xffffffffu, dw, o);
            nn += __shfl_xor_sync(0xffffffffu, nn, o);
        }
        if (lane == 0) {
            float mi = 1.f / (sqrtf(nn) + EPSF);
            s_simr[n] = dr * s_nrm[0] * mi;
            s_simw[n] = dw * s_nrm[1] * mi;
        }
    }
    __syncthreads();

    if (tid < 2) {
        const float* sims = tid ? s_simw : s_simr;
        float* wout = tid ? s_ws : s_wr;
        int*   iout = tid ? s_iw : s_ir;
        unsigned used = 0;
        float vals[4];
        #pragma unroll
        for (int k = 0; k < 4; k++) {
            float best = -1e30f; int bi = 0;
            for (int n = 0; n < MEMN; n++) {
                if (!((used >> n) & 1u) && sims[n] > best) { best = sims[n]; bi = n; }
            }
            used |= 1u << bi;
            iout[k] = bi; vals[k] = best;
        }
        float mx = vals[0], ssum = 0.f, e[4];
        #pragma unroll
        for (int k = 0; k < 4; k++) { e[k] = expf(vals[k] - mx); ssum += e[k]; }
        #pragma unroll
        for (int k = 0; k < 4; k++) wout[k] = e[k] / ssum;
    }
    __syncthreads();

    float r = 0.f;
    #pragma unroll
    for (int k = 0; k < 4; k++)
        r += s_wr[k] * g_M[(b*MEMN + s_ir[k])*KSZ + tid];
    g_r[b*KSZ + tid] = r;
    s_rnew[tid] = r;

    #pragma unroll
    for (int k = 0; k < 4; k++)
        g_M[(b*MEMN + s_iw[k])*KSZ + tid] += s_ws[k] * vv;

    if (t == TT - 1) {
        __syncthreads();
        if (wid < 4) {
            const float* wrow = wo + wid*512;
            float p = 0.f;
            for (int j = lane; j < 256; j += 32) p += wrow[j]       * g_hst[b*HH + j];
            for (int j = lane; j < 256; j += 32) p += wrow[256 + j] * s_rnew[j];
            #pragma unroll
            for (int o = 16; o > 0; o >>= 1) p += __shfl_xor_sync(0xffffffffu, p, o);
            if (lane == 0) s_y[wid] = p + wob[wid];
        }
        __syncthreads();
        if (tid < 4 && (b*4 + tid) < out_size) out[b*4 + tid] = s_y[tid];
        if (tid == 0 && out_size >= BB*YY + BB) {
            int am = 0; float bv = s_y[0];
            #pragma unroll
            for (int o = 1; o < 4; o++) if (s_y[o] > bv) { bv = s_y[o]; am = o; }
            out[BB*YY + b] = (float)am;
        }
    }
}

// ---------------- launch ----------------
extern "C" void kernel_launch(void* const* d_in, const int* in_sizes, int n_in,
                              void* d_out, int out_size)
{
    const float* x    = (const float*)d_in[0];
    const float* c1w  = (const float*)d_in[1];
    const float* c1b  = (const float*)d_in[2];
    const float* c2w  = (const float*)d_in[3];
    const float* c2b  = (const float*)d_in[4];
    const float* c3w  = (const float*)d_in[5];
    const float* c3b  = (const float*)d_in[6];
    const float* fc1w = (const float*)d_in[7];
    const float* fc1b = (const float*)d_in[8];
    const float* fc2w = (const float*)d_in[9];
    const float* fc2b = (const float*)d_in[10];
    const float* gamma= (const float*)d_in[11];
    const float* beta = (const float*)d_in[12];
    const float* lwi  = (const float*)d_in[13];
    const float* lwh  = (const float*)d_in[14];
    const float* lb   = (const float*)d_in[15];
    const float* wk   = (const float*)d_in[16];
    const float* wwk  = (const float*)d_in[17];
    const float* wv   = (const float*)d_in[18];
    const float* wo   = (const float*)d_in[19];
    const float* wob  = (const float*)d_in[20];
    const float* mem0 = (const float*)d_in[21];
    float* out = (float*)d_out;

    cudaFuncSetAttribute(k_convf, cudaFuncAttributeMaxDynamicSharedMemorySize,
                         CONVF_SMEM_FLOATS * 4);
    cudaFuncSetAttribute(k_tcs, cudaFuncAttributeMaxDynamicSharedMemorySize,
                         TCS_SMEM_BYTES);

    float *p_h3, *p_fc1, *p_fc2p, *p_z, *p_gz, *p_g4, *p_hp, *p_h;
    float *p_wcat, *p_wz, *p_whead, *p_w2r, *p_w3r;
    cudaGetSymbolAddress((void**)&p_h3,    g_h3);
    cudaGetSymbolAddress((void**)&p_fc1,   g_fc1);
    cudaGetSymbolAddress((void**)&p_fc2p,  g_fc2p);
    cudaGetSymbolAddress((void**)&p_z,     g_z);
    cudaGetSymbolAddress((void**)&p_gz,    g_gz);
    cudaGetSymbolAddress((void**)&p_g4,    g_gates4);
    cudaGetSymbolAddress((void**)&p_hp,    g_hpart);
    cudaGetSymbolAddress((void**)&p_h,     g_hst);
    cudaGetSymbolAddress((void**)&p_wcat,  g_Wcat);
    cudaGetSymbolAddress((void**)&p_wz,    g_Wz);
    cudaGetSymbolAddress((void**)&p_whead, g_Whead);
    cudaGetSymbolAddress((void**)&p_w2r,   g_w2r);
    cudaGetSymbolAddress((void**)&p_w3r,   g_w3r);

    k_setup<<<(BB*MEMN*KSZ + 255)/256, 256>>>(mem0, lwi, lwh, wk, wwk, wv,
                                              c2w, c3w, out, out_size);

    // encoder (tensor-core conv)
    k_convf<<<NFRM, 256, CONVF_SMEM_FLOATS * 4>>>(x, c1w, c1b, p_w2r, c2b, p_w3r, c3b);
    // fc1: [5120,512]@[256,512]^T + b -> relu (chunked k_tc, K=512)
    k_tc<<<dim3(2, 80), 256>>>(p_h3, 512, fc1w, 512, fc1b, p_fc1, 256, 512, 2);
    // fc2: split-K x2 partials (single-stage); combine in ctxnorm
    k_tcs<<<dim3(1, 80, 2), 256, TCS_SMEM_BYTES>>>(p_fc1, 256, fc2w, 256, nullptr,
                                                   p_fc2p, 128, NFRM*DD, 0, 0);
    k_ctxnorm<<<BB, 128>>>(fc2b, gamma, beta);
    // Gz = z @ Wz^T + lstm_b (single-stage, K=128)
    k_tcs<<<dim3(8, 80, 1), 256, TCS_SMEM_BYTES>>>(p_z, 128, p_wz, 128, lb,
                                                   p_gz, 1024, 0, 0, 1);

    for (int t = 0; t < TT; t++) {
        // gates: [r|h] @ Wcat^T, split-K x4, single-stage
        k_tcs<<<dim3(8, 4, 4), 256, TCS_SMEM_BYTES>>>(nullptr, 0, p_wcat, 512, nullptr,
                                                      p_g4, 1024, BB*1024, 1, 0);
        k_lstm<<<64, 256>>>(t);
        // heads: h @ Whead^T, split-K x2, single-stage
        k_tcs<<<dim3(6, 4, 2), 256, TCS_SMEM_BYTES>>>(p_h, 256, p_whead, 256, nullptr,
                                                      p_hp, 768, BB*768, 0, 0);
        k_mem<<<BB, 256>>>(t, wo, wob, out, out_size);
    }
}